// round 1
// baseline (speedup 1.0000x reference)
#include <cuda_runtime.h>
#include <math.h>
#include <stdint.h>

#define NSP   8192
#define LEN   512
#define HD    768
#define MAXW  30
#define FFD   3000
#define MD    2324      // 3*768+20
#define KTOP  204
#define CANT  50
#define PROWS 10200     // KTOP*CANT
#define PPAD  10240
#define PD    7052      // 3*MD+80
#define NEG9  (-1e9f)
#define NCB   24        // ceil(FFD/128) column blocks

// ---------------- scratch (static device globals; no allocation) ----------------
__device__ float g_base[(size_t)NSP * MD];        // 76 MB
__device__ int   g_w[NSP];
__device__ int   g_s[NSP];
__device__ float g_m[NSP];
__device__ float g_wscore[MAXW];
__device__ unsigned long long g_keys[NSP];
__device__ int   g_topidx[KTOP];
__device__ float g_topm[KTOP];
__device__ int   g_topspk[KTOP];
__device__ int   g_topseg[KTOP];
__device__ float g_topbase[(size_t)KTOP * MD];
__device__ float g_src[(size_t)KTOP * MD];
__device__ float g_cp[KTOP * KTOP];
__device__ float g_antsc[KTOP * CANT];
__device__ int   g_antpos[KTOP * CANT];
__device__ float g_pair[(size_t)PPAD * PD];       // 288 MB
__device__ float g_fine[PPAD];
__device__ float g_part[(size_t)PPAD * NCB];

// orderable key: primary = value descending, secondary = index ascending
__device__ __forceinline__ unsigned long long make_key(float v, unsigned idx) {
    unsigned u = __float_as_uint(v);
    u = (u & 0x80000000u) ? ~u : (u | 0x80000000u);
    return ((unsigned long long)u << 32) | (unsigned)(0xFFFFFFFFu - idx);
}
__device__ __forceinline__ int key_idx(unsigned long long k) {
    return (int)(0xFFFFFFFFu - (unsigned)(k & 0xFFFFFFFFu));
}

// ---------------- 1) span extraction + head attention + base embedding ----------------
__global__ void span_prep(const float* __restrict__ h, const int* __restrict__ spans,
                          const float* __restrict__ w_head, const float* __restrict__ b_head,
                          const float* __restrict__ width_emb)
{
    int n = blockIdx.x;
    int tid = threadIdx.x;            // 128 threads
    int lane = tid & 31, warp = tid >> 5;
    __shared__ float sc[32];
    __shared__ float wts[32];
    __shared__ int shr[3];            // s, e, w
    if (tid == 0) {
        int s = spans[2 * n], e = spans[2 * n + 1];
        s = min(max(s, 0), LEN - 1);
        e = min(max(e, 0), LEN - 1);
        int w = e - s + 1;
        if (w < 1) w = 1;
        if (w > MAXW) w = MAXW;
        shr[0] = s; shr[1] = e; shr[2] = w;
        g_s[n] = s; g_w[n] = w;
    }
    __syncthreads();
    int s = shr[0], e = shr[1], w = shr[2];

    // attention scores over valid width positions
    for (int wp = warp; wp < w; wp += 4) {
        const float* row = h + (size_t)(s + wp) * HD;
        float acc = 0.f;
        for (int c = lane; c < HD; c += 32) acc += row[c] * w_head[c];
        #pragma unroll
        for (int o = 16; o > 0; o >>= 1) acc += __shfl_down_sync(0xffffffffu, acc, o);
        if (lane == 0) sc[wp] = acc + b_head[0];
    }
    __syncthreads();
    if (warp == 0) {
        float v = (lane < w) ? sc[lane] : -1e30f;
        float mx = v;
        #pragma unroll
        for (int o = 16; o > 0; o >>= 1) mx = fmaxf(mx, __shfl_xor_sync(0xffffffffu, mx, o));
        float p = (lane < w) ? expf(v - mx) : 0.f;
        float sm = p;
        #pragma unroll
        for (int o = 16; o > 0; o >>= 1) sm += __shfl_xor_sync(0xffffffffu, sm, o);
        wts[lane] = p / sm;
    }
    __syncthreads();

    size_t bo = (size_t)n * MD;
    const float* hs = h + (size_t)s * HD;
    const float* he = h + (size_t)e * HD;
    for (int c = tid; c < HD; c += 128) {
        float acc = 0.f;
        for (int wp = 0; wp < w; wp++) acc += wts[wp] * h[(size_t)(s + wp) * HD + c];
        g_base[bo + c]          = hs[c];
        g_base[bo + HD + c]     = he[c];
        g_base[bo + 2 * HD + c] = acc;
    }
    if (tid < 20) g_base[bo + 3 * HD + tid] = width_emb[(w - 1) * 20 + tid];
}

// ---------------- 2) width-prior MLP (only 30 distinct widths) ----------------
__global__ void width_scores(const float* __restrict__ wprior, const float* __restrict__ w0,
                             const float* __restrict__ b0, const float* __restrict__ w1,
                             const float* __restrict__ b1)
{
    int w = blockIdx.x;               // 0..29
    int tid = threadIdx.x;            // 256
    __shared__ float wv[20];
    __shared__ float red[256];
    if (tid < 20) wv[tid] = wprior[w * 20 + tid];
    __syncthreads();
    float acc = 0.f;
    for (int f = tid; f < FFD; f += 256) {
        float d = b0[f];
        #pragma unroll
        for (int k = 0; k < 20; k++) d += wv[k] * w0[k * FFD + f];
        acc += fmaxf(d, 0.f) * w1[f];
    }
    red[tid] = acc;
    __syncthreads();
    for (int o = 128; o > 0; o >>= 1) { if (tid < o) red[tid] += red[tid + o]; __syncthreads(); }
    if (tid == 0) g_wscore[w] = red[0] + b1[0];
}

__global__ void m_init(const float* __restrict__ mb1)
{
    int n = blockIdx.x * 256 + threadIdx.x;
    if (n < NSP) g_m[n] = mb1[0] + g_wscore[g_w[n] - 1];
}

// ---------------- 3) fused MLP-score GEMM:  out_partial = relu(A@W0+b0) . w1 ----------------
// which=0: A=g_base (mention), which=1: A=g_pair (fine). BM=BN=128, BK=8, 256 thr.
__global__ __launch_bounds__(256) void mlp_gemm(const float* __restrict__ W0,
                                                const float* __restrict__ b0,
                                                const float* __restrict__ w1,
                                                int which, int R, int D)
{
    const float* A = which ? g_pair : g_base;
    __shared__ float As[8][128];
    __shared__ float Bs[8][128];
    __shared__ float rowsum[128];
    int tid = threadIdx.x;
    int row0 = blockIdx.y * 128, col0 = blockIdx.x * 128;
    int arow = tid >> 1, acol = (tid & 1) * 4;
    int brow = tid >> 5, bcol = (tid & 31) * 4;
    int ty = tid >> 4, tx = tid & 15;
    float acc[8][8];
    #pragma unroll
    for (int i = 0; i < 8; i++)
        #pragma unroll
        for (int j = 0; j < 8; j++) acc[i][j] = 0.f;

    int ktiles = (D + 7) / 8;
    for (int kt = 0; kt < ktiles; kt++) {
        int k0 = kt * 8;
        {
            int r = row0 + arow, k = k0 + acol;
            float4 v = make_float4(0.f, 0.f, 0.f, 0.f);
            if (r < R && k < D) v = *(const float4*)(A + (size_t)r * D + k);  // D % 4 == 0
            As[acol + 0][arow] = v.x; As[acol + 1][arow] = v.y;
            As[acol + 2][arow] = v.z; As[acol + 3][arow] = v.w;
        }
        {
            int k = k0 + brow, c = col0 + bcol;
            float4 v = make_float4(0.f, 0.f, 0.f, 0.f);
            if (k < D && c < FFD) v = *(const float4*)(W0 + (size_t)k * FFD + c);
            *(float4*)&Bs[brow][bcol] = v;
        }
        __syncthreads();
        #pragma unroll
        for (int k = 0; k < 8; k++) {
            float ra[8], rb[8];
            #pragma unroll
            for (int j = 0; j < 8; j++) { ra[j] = As[k][ty * 8 + j]; rb[j] = Bs[k][tx * 8 + j]; }
            #pragma unroll
            for (int i = 0; i < 8; i++)
                #pragma unroll
                for (int j = 0; j < 8; j++) acc[i][j] += ra[i] * rb[j];
        }
        __syncthreads();
    }
    // fused epilogue: relu(+b0) * w1, reduce over the 128 ff columns of this block
    if (tid < 128) rowsum[tid] = 0.f;
    __syncthreads();
    float b0v[8], w1v[8];
    #pragma unroll
    for (int j = 0; j < 8; j++) {
        int f = col0 + tx * 8 + j;
        bool in = f < FFD;
        b0v[j] = in ? b0[f] : 0.f;
        w1v[j] = in ? w1[f] : 0.f;
    }
    #pragma unroll
    for (int i = 0; i < 8; i++) {
        float p = 0.f;
        #pragma unroll
        for (int j = 0; j < 8; j++) p += fmaxf(acc[i][j] + b0v[j], 0.f) * w1v[j];
        atomicAdd(&rowsum[ty * 8 + i], p);
    }
    __syncthreads();
    if (tid < 128) {
        int r = row0 + tid;
        if (r < R) g_part[(size_t)r * NCB + blockIdx.x] = rowsum[tid];
    }
}

__global__ void mlp_reduce(int which, int R)
{
    int r = blockIdx.x * 256 + threadIdx.x;
    if (r >= R) return;
    float acc = 0.f;
    for (int c = 0; c < NCB; c++) acc += g_part[(size_t)r * NCB + c];
    if (which) g_fine[r] += acc; else g_m[r] += acc;
}

// ---------------- 4) top-K mentions: bitonic sort of 8192 packed keys ----------------
__global__ void topk_mentions(const int* __restrict__ spk, const int* __restrict__ sent)
{
    int tid = threadIdx.x;            // 1024
    for (int i = tid; i < NSP; i += 1024) g_keys[i] = make_key(g_m[i], (unsigned)i);
    __syncthreads();
    for (unsigned k = 2; k <= NSP; k <<= 1)
        for (unsigned j = k >> 1; j > 0; j >>= 1) {
            for (unsigned i = tid; i < NSP; i += 1024) {
                unsigned ixj = i ^ j;
                if (ixj > i) {
                    unsigned long long a = g_keys[i], b = g_keys[ixj];
                    bool desc = ((i & k) == 0);
                    if (desc ? (a < b) : (a > b)) { g_keys[i] = b; g_keys[ixj] = a; }
                }
            }
            __syncthreads();
        }
    // first KTOP keys = top mentions; sort their span-indices ascending (document order)
    __shared__ int tix[256];
    for (int t = tid; t < 256; t += 1024)
        tix[t] = (t < KTOP) ? key_idx(g_keys[t]) : 0x7FFFFFFF;
    __syncthreads();
    for (unsigned k = 2; k <= 256; k <<= 1)
        for (unsigned j = k >> 1; j > 0; j >>= 1) {
            for (unsigned t = tid; t < 256; t += 1024) {
                unsigned ixj = t ^ j;
                if (ixj > t) {
                    int a = tix[t], b = tix[ixj];
                    bool asc = ((t & k) == 0);
                    if (asc ? (a > b) : (a < b)) { tix[t] = b; tix[ixj] = a; }
                }
            }
            __syncthreads();
        }
    if (tid < KTOP) {
        int idx = tix[tid];
        g_topidx[tid] = idx;
        g_topm[tid]   = g_m[idx];
        int s = g_s[idx];
        g_topspk[tid] = spk[s];
        g_topseg[tid] = sent[s];
    }
}

__global__ void gather_topbase()
{
    int i = blockIdx.x;
    const float* src = g_base + (size_t)g_topidx[i] * MD;
    float* dst = g_topbase + (size_t)i * MD;
    for (int d = threadIdx.x; d < MD; d += 256) dst[d] = src[d];
}

// ---------------- 5) src = top_base @ c2_w + c2_b  (plain GEMM) ----------------
__global__ __launch_bounds__(256) void src_gemm(const float* __restrict__ c2w,
                                                const float* __restrict__ c2b)
{
    __shared__ float As[8][128];
    __shared__ float Bs[8][128];
    int tid = threadIdx.x;
    int row0 = blockIdx.y * 128, col0 = blockIdx.x * 128;
    int arow = tid >> 1, acol = (tid & 1) * 4;
    int brow = tid >> 5, bcol = (tid & 31) * 4;
    int ty = tid >> 4, tx = tid & 15;
    float acc[8][8];
    #pragma unroll
    for (int i = 0; i < 8; i++)
        #pragma unroll
        for (int j = 0; j < 8; j++) acc[i][j] = 0.f;

    int ktiles = (MD + 7) / 8;
    for (int kt = 0; kt < ktiles; kt++) {
        int k0 = kt * 8;
        {
            int r = row0 + arow, k = k0 + acol;
            float4 v = make_float4(0.f, 0.f, 0.f, 0.f);
            if (r < KTOP && k < MD) v = *(const float4*)(g_topbase + (size_t)r * MD + k);
            As[acol + 0][arow] = v.x; As[acol + 1][arow] = v.y;
            As[acol + 2][arow] = v.z; As[acol + 3][arow] = v.w;
        }
        {
            int k = k0 + brow, c = col0 + bcol;
            float4 v = make_float4(0.f, 0.f, 0.f, 0.f);
            if (k < MD && c < MD) v = *(const float4*)(c2w + (size_t)k * MD + c);
            *(float4*)&Bs[brow][bcol] = v;
        }
        __syncthreads();
        #pragma unroll
        for (int k = 0; k < 8; k++) {
            float ra[8], rb[8];
            #pragma unroll
            for (int j = 0; j < 8; j++) { ra[j] = As[k][ty * 8 + j]; rb[j] = Bs[k][tx * 8 + j]; }
            #pragma unroll
            for (int i = 0; i < 8; i++)
                #pragma unroll
                for (int j = 0; j < 8; j++) acc[i][j] += ra[i] * rb[j];
        }
        __syncthreads();
    }
    #pragma unroll
    for (int i = 0; i < 8; i++) {
        int r = row0 + ty * 8 + i;
        if (r >= KTOP) continue;
        #pragma unroll
        for (int j = 0; j < 8; j++) {
            int c = col0 + tx * 8 + j;
            if (c < MD) g_src[(size_t)r * MD + c] = acc[i][j] + c2b[c];
        }
    }
}

// ---------------- 6) coarse pair scores cp[i][j] ----------------
__global__ void cp_kernel()
{
    __shared__ float As[16][17];
    __shared__ float Bs[16][17];
    int tx = threadIdx.x, ty = threadIdx.y;
    int i0 = blockIdx.y * 16, j0 = blockIdx.x * 16;
    int i = i0 + ty, j = j0 + tx;
    float acc = 0.f;
    for (int k0 = 0; k0 < MD; k0 += 16) {
        int k = k0 + tx;
        As[ty][tx] = (i0 + ty < KTOP && k < MD) ? g_src[(size_t)(i0 + ty) * MD + k] : 0.f;
        Bs[ty][tx] = (j0 + ty < KTOP && k < MD) ? g_topbase[(size_t)(j0 + ty) * MD + k] : 0.f;
        __syncthreads();
        #pragma unroll
        for (int kk = 0; kk < 16; kk++) acc += As[ty][kk] * Bs[tx][kk];
        __syncthreads();
    }
    if (i < KTOP && j < KTOP) {
        float v = acc + g_topm[i] + g_topm[j];
        if (j >= i) v = NEG9;
        g_cp[i * KTOP + j] = v;
    }
}

// ---------------- 7) per-row top-C antecedents ----------------
__global__ void topc()
{
    int i = blockIdx.x;
    int tid = threadIdx.x;            // 128
    __shared__ unsigned long long keys[256];
    for (int t = tid; t < 256; t += 128)
        keys[t] = (t < KTOP) ? make_key(g_cp[i * KTOP + t], (unsigned)t) : 0ull;
    __syncthreads();
    for (unsigned k = 2; k <= 256; k <<= 1)
        for (unsigned j = k >> 1; j > 0; j >>= 1) {
            for (unsigned t = tid; t < 256; t += 128) {
                unsigned ixj = t ^ j;
                if (ixj > t) {
                    unsigned long long a = keys[t], b = keys[ixj];
                    bool desc = ((t & k) == 0);
                    if (desc ? (a < b) : (a > b)) { keys[t] = b; keys[ixj] = a; }
                }
            }
            __syncthreads();
        }
    if (tid < CANT) {
        int pos = key_idx(keys[tid]);
        g_antpos[i * CANT + tid] = pos;
        g_antsc[i * CANT + tid] = g_cp[i * KTOP + pos];
    }
}

// ---------------- 8) build pair_in rows ----------------
__global__ void pack_pair(const float* __restrict__ spk_emb, const float* __restrict__ seg_emb,
                          const float* __restrict__ gen_emb, const float* __restrict__ dist_emb,
                          const int* __restrict__ gen_ids)
{
    int r = blockIdx.x;               // 0..PPAD-1
    int tid = threadIdx.x;            // 256
    size_t ro = (size_t)r * PD;
    if (r >= PROWS) {
        for (int d = tid; d < PD; d += 256) g_pair[ro + d] = 0.f;
        return;
    }
    int i = r / CANT, c = r % CANT;
    int p = g_antpos[i * CANT + c];
    const float* bi = g_topbase + (size_t)i * MD;
    const float* bj = g_topbase + (size_t)p * MD;
    for (int d = tid; d < MD; d += 256) {
        float a = bi[d], b = bj[d];
        g_pair[ro + d]          = a;
        g_pair[ro + MD + d]     = b;
        g_pair[ro + 2 * MD + d] = a * b;
    }
    if (tid < 20) {
        int same = (g_topspk[i] == g_topspk[p]) ? 1 : 0;
        int off = i - p; if (off < 0) off = 0;
        int bk = off >= 64 ? 9 : off >= 32 ? 8 : off >= 16 ? 7 : off >= 8 ? 6 : off >= 5 ? 5 : off;
        int ds = g_topseg[i] - g_topseg[p]; ds = min(max(ds, 0), 2);
        int g = gen_ids[0];
        g_pair[ro + 3 * MD + tid]      = spk_emb[same * 20 + tid];
        g_pair[ro + 3 * MD + 20 + tid] = gen_emb[g * 20 + tid];
        g_pair[ro + 3 * MD + 40 + tid] = dist_emb[bk * 20 + tid];
        g_pair[ro + 3 * MD + 60 + tid] = seg_emb[ds * 20 + tid];
    }
}

__global__ void fine_init(const float* __restrict__ ab1)
{
    int r = blockIdx.x * 256 + threadIdx.x;
    if (r < PPAD) g_fine[r] = ab1[0];
}

// ---------------- 9) final output ----------------
__global__ void final_out(float* __restrict__ out, const float* __restrict__ dummy)
{
    int i = blockIdx.x;
    int tid = threadIdx.x;            // 64
    if (tid == 0) out[i * (CANT + 1)] = dummy[0];
    if (tid < CANT) {
        int p = g_antpos[i * CANT + tid];
        bool valid = p < i;
        out[i * (CANT + 1) + 1 + tid] =
            valid ? (g_antsc[i * CANT + tid] + g_fine[i * CANT + tid] * 2.0f) : NEG9;
    }
}

// ---------------- launch ----------------
extern "C" void kernel_launch(void* const* d_in, const int* in_sizes, int n_in,
                              void* d_out, int out_size)
{
    const float* h          = (const float*)d_in[0];
    const int*   spans      = (const int*)  d_in[1];
    const int*   spk_ids    = (const int*)  d_in[2];
    const int*   gen_ids    = (const int*)  d_in[3];
    const int*   sent_map   = (const int*)  d_in[4];
    const float* w_head     = (const float*)d_in[5];
    const float* b_head     = (const float*)d_in[6];
    const float* width_emb  = (const float*)d_in[7];
    const float* width_prior= (const float*)d_in[8];
    const float* speaker_emb= (const float*)d_in[9];
    const float* segment_emb= (const float*)d_in[10];
    const float* genre_emb  = (const float*)d_in[11];
    const float* dist_emb   = (const float*)d_in[12];
    const float* mention_w0 = (const float*)d_in[13];
    const float* mention_b0 = (const float*)d_in[14];
    const float* mention_w1 = (const float*)d_in[15];
    const float* mention_b1 = (const float*)d_in[16];
    const float* width_w0   = (const float*)d_in[17];
    const float* width_b0   = (const float*)d_in[18];
    const float* width_w1   = (const float*)d_in[19];
    const float* width_b1   = (const float*)d_in[20];
    const float* c2_w       = (const float*)d_in[21];
    const float* c2_b       = (const float*)d_in[22];
    const float* ant_w0     = (const float*)d_in[23];
    const float* ant_b0     = (const float*)d_in[24];
    const float* ant_w1     = (const float*)d_in[25];
    const float* ant_b1     = (const float*)d_in[26];
    const float* dummy_bias = (const float*)d_in[27];
    float* out = (float*)d_out;

    span_prep<<<NSP, 128>>>(h, spans, w_head, b_head, width_emb);
    width_scores<<<MAXW, 256>>>(width_prior, width_w0, width_b0, width_w1, width_b1);
    m_init<<<(NSP + 255) / 256, 256>>>(mention_b1);

    dim3 gm(NCB, NSP / 128);
    mlp_gemm<<<gm, 256>>>(mention_w0, mention_b0, mention_w1, 0, NSP, MD);
    mlp_reduce<<<(NSP + 255) / 256, 256>>>(0, NSP);

    topk_mentions<<<1, 1024>>>(spk_ids, sent_map);
    gather_topbase<<<KTOP, 256>>>();

    dim3 gs((MD + 127) / 128, (KTOP + 127) / 128);
    src_gemm<<<gs, 256>>>(c2_w, c2_b);

    dim3 gc((KTOP + 15) / 16, (KTOP + 15) / 16);
    cp_kernel<<<gc, dim3(16, 16)>>>();
    topc<<<KTOP, 128>>>();

    pack_pair<<<PPAD, 256>>>(speaker_emb, segment_emb, genre_emb, dist_emb, gen_ids);
    fine_init<<<PPAD / 256, 256>>>(ant_b1);

    dim3 gf(NCB, PPAD / 128);
    mlp_gemm<<<gf, 256>>>(ant_w0, ant_b0, ant_w1, 1, PPAD, PD);
    mlp_reduce<<<(PPAD + 255) / 256, 256>>>(1, PPAD);

    final_out<<<KTOP, 64>>>(out, dummy_bias);
}

// round 3
// speedup vs baseline: 6.6431x; 6.6431x over previous
#include <cuda_runtime.h>
#include <cuda_bf16.h>
#include <math.h>
#include <stdint.h>

#define NSP   8192
#define LEN   512
#define HD    768
#define MAXW  30
#define FFD   3000
#define MD    2324      // 3*768+20
#define KTOP  204
#define CANT  50
#define PROWS 10200     // KTOP*CANT
#define PPAD  10240
#define NEG9  (-1e9f)

#define KPAD  2336      // MD padded to multiple of 32
#define FFP   3072      // FFD padded to multiple of 128
#define NCB   24        // FFP/128 column blocks
#define BM    128
#define BN    128
#define BKK   32
#define SECT  ((size_t)KPAD * FFP)

// ---------------- scratch (static device globals; zero-initialized) ----------------
__device__ float          g_base[(size_t)NSP * MD];        // fp32 base (for top gather)
__device__ __nv_bfloat16  g_baseh[(size_t)NSP * KPAD];     // bf16 base, padded
__device__ __nv_bfloat16  g_w0h[(size_t)KPAD * FFP];       // mention_w0 bf16 padded
__device__ __nv_bfloat16  g_aw0h[3 * (size_t)KPAD * FFP];  // ant_w0 sections a,b,c
__device__ int   g_w[NSP];
__device__ int   g_s[NSP];
__device__ float g_m[NSP];
__device__ float g_wscore[MAXW];
__device__ unsigned long long g_keys[NSP];
__device__ int   g_topidx[KTOP];
__device__ float g_topm[KTOP];
__device__ int   g_topspk[KTOP];
__device__ int   g_topseg[KTOP];
__device__ float g_topbase[(size_t)KTOP * MD];
__device__ __nv_bfloat16 g_topbaseh[(size_t)256 * KPAD];   // padded rows (204..255 stay 0)
__device__ float g_src[(size_t)KTOP * MD];
__device__ float g_cp[KTOP * KTOP];
__device__ float g_antsc[KTOP * CANT];
__device__ int   g_antpos[KTOP * CANT];
__device__ float g_uabA[(size_t)KTOP * FFP];
__device__ float g_uabB[(size_t)KTOP * FFP];
__device__ float g_ftab[22 * FFP];                         // per-table projections
__device__ float g_feat[60 * FFP];                         // combined feature rows
__device__ float g_fine[PPAD];
__device__ float g_part[(size_t)PPAD * NCB];

// orderable key: primary = value descending, secondary = index ascending
__device__ __forceinline__ unsigned long long make_key(float v, unsigned idx) {
    unsigned u = __float_as_uint(v);
    u = (u & 0x80000000u) ? ~u : (u | 0x80000000u);
    return ((unsigned long long)u << 32) | (unsigned)(0xFFFFFFFFu - idx);
}
__device__ __forceinline__ int key_idx(unsigned long long k) {
    return (int)(0xFFFFFFFFu - (unsigned)(k & 0xFFFFFFFFu));
}

// ---------------- weight conversions fp32 -> padded bf16 ----------------
__global__ void conv_w0(const float* __restrict__ w0)
{
    size_t idx = (size_t)blockIdx.x * 256 + threadIdx.x;
    if (idx >= (size_t)KPAD * FFP) return;
    int d = (int)(idx / FFP), f = (int)(idx % FFP);
    float v = (d < MD && f < FFD) ? w0[(size_t)d * FFD + f] : 0.f;
    g_w0h[idx] = __float2bfloat16(v);
}
__global__ void conv_aw0(const float* __restrict__ w0)
{
    size_t idx = (size_t)blockIdx.x * 256 + threadIdx.x;
    if (idx >= 3 * (size_t)KPAD * FFP) return;
    size_t per = (size_t)KPAD * FFP;
    int s = (int)(idx / per);
    size_t rem = idx % per;
    int d = (int)(rem / FFP), f = (int)(rem % FFP);
    float v = (d < MD && f < FFD) ? w0[(size_t)(s * MD + d) * FFD + f] : 0.f;
    g_aw0h[idx] = __float2bfloat16(v);
}

// ---------------- 1) span extraction + head attention + base embedding ----------------
__global__ void span_prep(const float* __restrict__ h, const int* __restrict__ spans,
                          const float* __restrict__ w_head, const float* __restrict__ b_head,
                          const float* __restrict__ width_emb)
{
    int n = blockIdx.x;
    int tid = threadIdx.x;            // 128 threads
    int lane = tid & 31, warp = tid >> 5;
    __shared__ float sc[32];
    __shared__ float wts[32];
    __shared__ int shr[3];
    if (tid == 0) {
        int s = spans[2 * n], e = spans[2 * n + 1];
        s = min(max(s, 0), LEN - 1);
        e = min(max(e, 0), LEN - 1);
        int w = e - s + 1;
        if (w < 1) w = 1;
        if (w > MAXW) w = MAXW;
        shr[0] = s; shr[1] = e; shr[2] = w;
        g_s[n] = s; g_w[n] = w;
    }
    __syncthreads();
    int s = shr[0], e = shr[1], w = shr[2];

    for (int wp = warp; wp < w; wp += 4) {
        const float* row = h + (size_t)(s + wp) * HD;
        float acc = 0.f;
        for (int c = lane; c < HD; c += 32) acc += row[c] * w_head[c];
        #pragma unroll
        for (int o = 16; o > 0; o >>= 1) acc += __shfl_down_sync(0xffffffffu, acc, o);
        if (lane == 0) sc[wp] = acc + b_head[0];
    }
    __syncthreads();
    if (warp == 0) {
        float v = (lane < w) ? sc[lane] : -1e30f;
        float mx = v;
        #pragma unroll
        for (int o = 16; o > 0; o >>= 1) mx = fmaxf(mx, __shfl_xor_sync(0xffffffffu, mx, o));
        float p = (lane < w) ? expf(v - mx) : 0.f;
        float sm = p;
        #pragma unroll
        for (int o = 16; o > 0; o >>= 1) sm += __shfl_xor_sync(0xffffffffu, sm, o);
        wts[lane] = p / sm;
    }
    __syncthreads();

    size_t bo = (size_t)n * MD;
    size_t bh = (size_t)n * KPAD;
    const float* hs = h + (size_t)s * HD;
    const float* he = h + (size_t)e * HD;
    for (int c = tid; c < HD; c += 128) {
        float acc = 0.f;
        for (int wp = 0; wp < w; wp++) acc += wts[wp] * h[(size_t)(s + wp) * HD + c];
        float v0 = hs[c], v1 = he[c];
        g_base[bo + c]          = v0;
        g_base[bo + HD + c]     = v1;
        g_base[bo + 2 * HD + c] = acc;
        g_baseh[bh + c]          = __float2bfloat16(v0);
        g_baseh[bh + HD + c]     = __float2bfloat16(v1);
        g_baseh[bh + 2 * HD + c] = __float2bfloat16(acc);
    }
    if (tid < 20) {
        float v = width_emb[(w - 1) * 20 + tid];
        g_base[bo + 3 * HD + tid]  = v;
        g_baseh[bh + 3 * HD + tid] = __float2bfloat16(v);
    }
}

// ---------------- 2) width-prior MLP ----------------
__global__ void width_scores(const float* __restrict__ wprior, const float* __restrict__ w0,
                             const float* __restrict__ b0, const float* __restrict__ w1,
                             const float* __restrict__ b1)
{
    int w = blockIdx.x;
    int tid = threadIdx.x;
    __shared__ float wv[20];
    __shared__ float red[256];
    if (tid < 20) wv[tid] = wprior[w * 20 + tid];
    __syncthreads();
    float acc = 0.f;
    for (int f = tid; f < FFD; f += 256) {
        float d = b0[f];
        #pragma unroll
        for (int k = 0; k < 20; k++) d += wv[k] * w0[k * FFD + f];
        acc += fmaxf(d, 0.f) * w1[f];
    }
    red[tid] = acc;
    __syncthreads();
    for (int o = 128; o > 0; o >>= 1) { if (tid < o) red[tid] += red[tid + o]; __syncthreads(); }
    if (tid == 0) g_wscore[w] = red[0] + b1[0];
}

__global__ void m_init(const float* __restrict__ mb1)
{
    int n = blockIdx.x * 256 + threadIdx.x;
    if (n < NSP) g_m[n] = mb1[0] + g_wscore[g_w[n] - 1];
}

// ---------------- PTX helpers ----------------
__device__ __forceinline__ void ldsm_x4(uint32_t* r, uint32_t addr) {
    asm volatile("ldmatrix.sync.aligned.m8n8.x4.shared.b16 {%0,%1,%2,%3}, [%4];"
                 : "=r"(r[0]), "=r"(r[1]), "=r"(r[2]), "=r"(r[3]) : "r"(addr));
}
__device__ __forceinline__ void ldsm_x4_t(uint32_t* r, uint32_t addr) {
    asm volatile("ldmatrix.sync.aligned.m8n8.x4.trans.shared.b16 {%0,%1,%2,%3}, [%4];"
                 : "=r"(r[0]), "=r"(r[1]), "=r"(r[2]), "=r"(r[3]) : "r"(addr));
}
__device__ __forceinline__ void mma_bf16(float* c, const uint32_t* a, uint32_t b0, uint32_t b1) {
    asm volatile("mma.sync.aligned.m16n8k16.row.col.f32.bf16.bf16.f32 "
                 "{%0,%1,%2,%3}, {%4,%5,%6,%7}, {%8,%9}, {%0,%1,%2,%3};"
                 : "+f"(c[0]), "+f"(c[1]), "+f"(c[2]), "+f"(c[3])
                 : "r"(a[0]), "r"(a[1]), "r"(a[2]), "r"(a[3]), "r"(b0), "r"(b1));
}

// ---------------- 3) bf16 tensor-core GEMM, 3 modes ----------------
// MODE 0: mention. A=g_baseh, B=g_w0h. Epilogue relu(acc+b0)*w1 -> g_part.
// MODE 1: fine pairwise. A row r = topbase[i]*topbase[p] (bf16). B=g_aw0h sec2.
//         Epilogue relu(acc + uabA[i] + uabB[p] + feat[code] + b0)*w1 -> g_part.
// MODE 2: plain. A=g_topbaseh, B=g_aw0h sec(blockIdx.z). C -> g_uabA / g_uabB.
template<int MODE>
__global__ __launch_bounds__(256, 1) void hgemm(
    const float* __restrict__ b0v, const float* __restrict__ w1v, int R)
{
    __shared__ __nv_bfloat16 As[2][BM][40];
    __shared__ __nv_bfloat16 Bs[2][BKK][136];
    __shared__ float rowsum[BM];
    __shared__ int sRi[BM], sRp[BM], sRc[BM];

    int bsec = (MODE == 2) ? blockIdx.z : 0;
    const __nv_bfloat16* B = (MODE == 0) ? g_w0h
                            : g_aw0h + (size_t)((MODE == 1) ? 2 : bsec) * SECT;

    int tid = threadIdx.x;
    int lane = tid & 31, warp = tid >> 5;
    int wm = warp >> 2, wn = warp & 3;
    int row0 = blockIdx.y * BM, col0 = blockIdx.x * BN;

    if (tid < BM) {
        rowsum[tid] = 0.f;
        if (MODE == 1) {
            int r = row0 + tid;
            int i = r / CANT; if (i > KTOP - 1) i = KTOP - 1;
            int p = (r < PROWS) ? g_antpos[r] : 0;
            sRi[tid] = i; sRp[tid] = p;
            int same = (g_topspk[i] == g_topspk[p]) ? 1 : 0;
            int off = i - p; if (off < 0) off = 0;
            int bk = off >= 64 ? 9 : off >= 32 ? 8 : off >= 16 ? 7 : off >= 8 ? 6 : off >= 5 ? 5 : off;
            int ds = g_topseg[i] - g_topseg[p]; ds = ds < 0 ? 0 : (ds > 2 ? 2 : ds);
            sRc[tid] = (same * 10 + bk) * 3 + ds;
        }
    }
    __syncthreads();

    float acc[4][4][4];
    #pragma unroll
    for (int a = 0; a < 4; a++)
        #pragma unroll
        for (int b = 0; b < 4; b++)
            #pragma unroll
            for (int c = 0; c < 4; c++) acc[a][b][c] = 0.f;

    uint4 ra[2], rb[2];
    const int KT = KPAD / BKK;    // 73

    auto load_regs = [&](int kt) {
        int k0 = kt * BKK;
        #pragma unroll
        for (int v = 0; v < 2; v++) {
            int idx = tid + v * 256;          // A: 512 vecs of 8 bf16
            int arow = idx >> 2, aseg = idx & 3;
            if (MODE == 1) {
                int rI = sRi[arow], rP = sRp[arow];
                size_t off = (size_t)k0 + aseg * 8;
                uint4 va = *(const uint4*)(g_topbaseh + (size_t)rI * KPAD + off);
                uint4 vb = *(const uint4*)(g_topbaseh + (size_t)rP * KPAD + off);
                __nv_bfloat162* pa = (__nv_bfloat162*)&va;
                __nv_bfloat162* pb = (__nv_bfloat162*)&vb;
                uint4 vo;
                __nv_bfloat162* po = (__nv_bfloat162*)&vo;
                #pragma unroll
                for (int q = 0; q < 4; q++) po[q] = __hmul2(pa[q], pb[q]);
                ra[v] = vo;
            } else {
                const __nv_bfloat16* Ap = (MODE == 0) ? g_baseh : g_topbaseh;
                ra[v] = *(const uint4*)(Ap + (size_t)(row0 + arow) * KPAD + k0 + aseg * 8);
            }
            int brow = idx >> 4, bseg = idx & 15;
            rb[v] = *(const uint4*)(B + (size_t)(k0 + brow) * FFP + col0 + bseg * 8);
        }
    };
    auto store_regs = [&](int buf) {
        #pragma unroll
        for (int v = 0; v < 2; v++) {
            int idx = tid + v * 256;
            int arow = idx >> 2, aseg = idx & 3;
            *(uint4*)&As[buf][arow][aseg * 8] = ra[v];
            int brow = idx >> 4, bseg = idx & 15;
            *(uint4*)&Bs[buf][brow][bseg * 8] = rb[v];
        }
    };

    load_regs(0);
    store_regs(0);
    __syncthreads();

    for (int kt = 0; kt < KT; kt++) {
        int cur = kt & 1;
        if (kt + 1 < KT) load_regs(kt + 1);
        #pragma unroll
        for (int kk = 0; kk < BKK; kk += 16) {
            uint32_t af[4][4];
            #pragma unroll
            for (int mf = 0; mf < 4; mf++) {
                uint32_t addr = (uint32_t)__cvta_generic_to_shared(
                    &As[cur][wm * 64 + mf * 16 + (lane & 15)][kk + ((lane >> 4) << 3)]);
                ldsm_x4(af[mf], addr);
            }
            uint32_t bfr[2][4];
            #pragma unroll
            for (int g = 0; g < 2; g++) {
                int krow = kk + (lane & 7) + ((lane & 8) ? 8 : 0);
                int bcol = wn * 32 + g * 16 + ((lane & 16) ? 8 : 0);
                uint32_t addr = (uint32_t)__cvta_generic_to_shared(&Bs[cur][krow][bcol]);
                ldsm_x4_t(bfr[g], addr);
            }
            #pragma unroll
            for (int mf = 0; mf < 4; mf++)
                #pragma unroll
                for (int nf = 0; nf < 4; nf++)
                    mma_bf16(acc[mf][nf], af[mf], bfr[nf >> 1][(nf & 1) * 2],
                             bfr[nf >> 1][(nf & 1) * 2 + 1]);
        }
        if (kt + 1 < KT) store_regs(cur ^ 1);
        __syncthreads();
    }

    if (MODE == 2) {
        float* outC = bsec ? g_uabB : g_uabA;
        #pragma unroll
        for (int mf = 0; mf < 4; mf++)
            #pragma unroll
            for (int rr = 0; rr < 2; rr++) {
                int r = row0 + wm * 64 + mf * 16 + (lane >> 2) + rr * 8;
                if (r >= R) continue;
                #pragma unroll
                for (int nf = 0; nf < 4; nf++) {
                    int f = col0 + wn * 32 + nf * 8 + (lane & 3) * 2;
                    outC[(size_t)r * FFP + f]     = acc[mf][nf][rr * 2];
                    outC[(size_t)r * FFP + f + 1] = acc[mf][nf][rr * 2 + 1];
                }
            }
        return;
    }

    // fused epilogue: relu(acc + bias terms) * w1, reduce over block columns
    #pragma unroll
    for (int mf = 0; mf < 4; mf++)
        #pragma unroll
        for (int rr = 0; rr < 2; rr++) {
            int lrow = wm * 64 + mf * 16 + (lane >> 2) + rr * 8;
            const float* uA = nullptr; const float* uB = nullptr; const float* uF = nullptr;
            if (MODE == 1) {
                uA = g_uabA + (size_t)sRi[lrow] * FFP;
                uB = g_uabB + (size_t)sRp[lrow] * FFP;
                uF = g_feat + (size_t)sRc[lrow] * FFP;
            }
            float part = 0.f;
            #pragma unroll
            for (int nf = 0; nf < 4; nf++)
                #pragma unroll
                for (int c = 0; c < 2; c++) {
                    int f = col0 + wn * 32 + nf * 8 + (lane & 3) * 2 + c;
                    float v = acc[mf][nf][rr * 2 + c];
                    if (f < FFD) v += b0v[f];
                    if (MODE == 1) v += uA[f] + uB[f] + uF[f];
                    float w1f = (f < FFD) ? w1v[f] : 0.f;
                    part += fmaxf(v, 0.f) * w1f;
                }
            atomicAdd(&rowsum[lrow], part);
        }
    __syncthreads();
    if (tid < BM) {
        int r = row0 + tid;
        if (r < R) g_part[(size_t)r * NCB + blockIdx.x] = rowsum[tid];
    }
}

__global__ void mlp_reduce(int which, int R)
{
    int r = blockIdx.x * 256 + threadIdx.x;
    if (r >= R) return;
    float acc = 0.f;
    for (int c = 0; c < NCB; c++) acc += g_part[(size_t)r * NCB + c];
    if (which) g_fine[r] += acc; else g_m[r] += acc;
}

// ---------------- 4) top-K mentions ----------------
__global__ void topk_mentions(const int* __restrict__ spk, const int* __restrict__ sent)
{
    int tid = threadIdx.x;            // 1024
    for (int i = tid; i < NSP; i += 1024) g_keys[i] = make_key(g_m[i], (unsigned)i);
    __syncthreads();
    for (unsigned k = 2; k <= NSP; k <<= 1)
        for (unsigned j = k >> 1; j > 0; j >>= 1) {
            for (unsigned i = tid; i < NSP; i += 1024) {
                unsigned ixj = i ^ j;
                if (ixj > i) {
                    unsigned long long a = g_keys[i], b = g_keys[ixj];
                    bool desc = ((i & k) == 0);
                    if (desc ? (a < b) : (a > b)) { g_keys[i] = b; g_keys[ixj] = a; }
                }
            }
            __syncthreads();
        }
    __shared__ int tix[256];
    for (int t = tid; t < 256; t += 1024)
        tix[t] = (t < KTOP) ? key_idx(g_keys[t]) : 0x7FFFFFFF;
    __syncthreads();
    for (unsigned k = 2; k <= 256; k <<= 1)
        for (unsigned j = k >> 1; j > 0; j >>= 1) {
            for (unsigned t = tid; t < 256; t += 1024) {
                unsigned ixj = t ^ j;
                if (ixj > t) {
                    int a = tix[t], b = tix[ixj];
                    bool asc = ((t & k) == 0);
                    if (asc ? (a > b) : (a < b)) { tix[t] = b; tix[ixj] = a; }
                }
            }
            __syncthreads();
        }
    if (tid < KTOP) {
        int idx = tix[tid];
        g_topidx[tid] = idx;
        g_topm[tid]   = g_m[idx];
        int s = g_s[idx];
        g_topspk[tid] = spk[s];
        g_topseg[tid] = sent[s];
    }
}

__global__ void gather_topbase()
{
    int i = blockIdx.x;               // KTOP blocks
    const float* src = g_base + (size_t)g_topidx[i] * MD;
    float* dst = g_topbase + (size_t)i * MD;
    __nv_bfloat16* dsh = g_topbaseh + (size_t)i * KPAD;
    for (int d = threadIdx.x; d < MD; d += 256) {
        float v = src[d];
        dst[d] = v;
        dsh[d] = __float2bfloat16(v);
    }
}

// ---------------- 5) src = top_base @ c2_w + c2_b  (fp32) ----------------
__global__ __launch_bounds__(256) void src_gemm(const float* __restrict__ c2w,
                                                const float* __restrict__ c2b)
{
    __shared__ float As[8][128];
    __shared__ float Bs[8][128];
    int tid = threadIdx.x;
    int row0 = blockIdx.y * 128, col0 = blockIdx.x * 128;
    int arow = tid >> 1, acol = (tid & 1) * 4;
    int brow = tid >> 5, bcol = (tid & 31) * 4;
    int ty = tid >> 4, tx = tid & 15;
    float acc[8][8];
    #pragma unroll
    for (int i = 0; i < 8; i++)
        #pragma unroll
        for (int j = 0; j < 8; j++) acc[i][j] = 0.f;

    int ktiles = (MD + 7) / 8;
    for (int kt = 0; kt < ktiles; kt++) {
        int k0 = kt * 8;
        {
            int r = row0 + arow, k = k0 + acol;
            float4 v = make_float4(0.f, 0.f, 0.f, 0.f);
            if (r < KTOP && k < MD) v = *(const float4*)(g_topbase + (size_t)r * MD + k);
            As[acol + 0][arow] = v.x; As[acol + 1][arow] = v.y;
            As[acol + 2][arow] = v.z; As[acol + 3][arow] = v.w;
        }
        {
            int k = k0 + brow, c = col0 + bcol;
            float4 v = make_float4(0.f, 0.f, 0.f, 0.f);
            if (k < MD && c < MD) v = *(const float4*)(c2w + (size_t)k * MD + c);
            *(float4*)&Bs[brow][bcol] = v;
        }
        __syncthreads();
        #pragma unroll
        for (int k = 0; k < 8; k++) {
            float rra[8], rrb[8];
            #pragma unroll
            for (int j = 0; j < 8; j++) { rra[j] = As[k][ty * 8 + j]; rrb[j] = Bs[k][tx * 8 + j]; }
            #pragma unroll
            for (int i = 0; i < 8; i++)
                #pragma unroll
                for (int j = 0; j < 8; j++) acc[i][j] += rra[i] * rrb[j];
        }
        __syncthreads();
    }
    #pragma unroll
    for (int i = 0; i < 8; i++) {
        int r = row0 + ty * 8 + i;
        if (r >= KTOP) continue;
        #pragma unroll
        for (int j = 0; j < 8; j++) {
            int c = col0 + tx * 8 + j;
            if (c < MD) g_src[(size_t)r * MD + c] = acc[i][j] + c2b[c];
        }
    }
}

// ---------------- 6) coarse pair scores ----------------
__global__ void cp_kernel()
{
    __shared__ float As[16][17];
    __shared__ float Bs[16][17];
    int tx = threadIdx.x, ty = threadIdx.y;
    int i0 = blockIdx.y * 16, j0 = blockIdx.x * 16;
    int i = i0 + ty, j = j0 + tx;
    float acc = 0.f;
    for (int k0 = 0; k0 < MD; k0 += 16) {
        int k = k0 + tx;
        As[ty][tx] = (i0 + ty < KTOP && k < MD) ? g_src[(size_t)(i0 + ty) * MD + k] : 0.f;
        Bs[ty][tx] = (j0 + ty < KTOP && k < MD) ? g_topbase[(size_t)(j0 + ty) * MD + k] : 0.f;
        __syncthreads();
        #pragma unroll
        for (int kk = 0; kk < 16; kk++) acc += As[ty][kk] * Bs[tx][kk];
        __syncthreads();
    }
    if (i < KTOP && j < KTOP) {
        float v = acc + g_topm[i] + g_topm[j];
        if (j >= i) v = NEG9;
        g_cp[i * KTOP + j] = v;
    }
}

// ---------------- 7) per-row top-C antecedents ----------------
__global__ void topc()
{
    int i = blockIdx.x;
    int tid = threadIdx.x;            // 128
    __shared__ unsigned long long keys[256];
    for (int t = tid; t < 256; t += 128)
        keys[t] = (t < KTOP) ? make_key(g_cp[i * KTOP + t], (unsigned)t) : 0ull;
    __syncthreads();
    for (unsigned k = 2; k <= 256; k <<= 1)
        for (unsigned j = k >> 1; j > 0; j >>= 1) {
            for (unsigned t = tid; t < 256; t += 128) {
                unsigned ixj = t ^ j;
                if (ixj > t) {
                    unsigned long long a = keys[t], b = keys[ixj];
                    bool desc = ((t & k) == 0);
                    if (desc ? (a < b) : (a > b)) { keys[t] = b; keys[ixj] = a; }
                }
            }
            __syncthreads();
        }
    if (tid < CANT) {
        int pos = key_idx(keys[tid]);
        g_antpos[i * CANT + tid] = pos;
        g_antsc[i * CANT + tid] = g_cp[i * KTOP + pos];
    }
}

// ---------------- 8) feature table projections ----------------
// rows 0-1: speaker, 2-8: genre, 9-18: dist, 19-21: segment
__global__ void featproj(const float* __restrict__ aw0,
                         const float* __restrict__ spk_emb, const float* __restrict__ gen_emb,
                         const float* __restrict__ dist_emb, const float* __restrict__ seg_emb)
{
    int row = blockIdx.x;             // 22
    int tid = threadIdx.x;            // 256
    const float* emb; int off;
    if (row < 2)       { emb = spk_emb  + row * 20;        off = 0; }
    else if (row < 9)  { emb = gen_emb  + (row - 2) * 20;  off = 20; }
    else if (row < 19) { emb = dist_emb + (row - 9) * 20;  off = 40; }
    else               { emb = seg_emb  + (row - 19) * 20; off = 60; }
    __shared__ float ev[20];
    if (tid < 20) ev[tid] = emb[tid];
    __syncthreads();
    for (int f = tid; f < FFP; f += 256) {
        float acc = 0.f;
        if (f < FFD) {
            #pragma unroll
            for (int k = 0; k < 20; k++)
                acc += ev[k] * aw0[(size_t)(3 * MD + off + k) * FFD + f];
        }
        g_ftab[(size_t)row * FFP + f] = acc;
    }
}

__global__ void featcomb(const int* __restrict__ gen_ids)
{
    int code = blockIdx.x;            // 60
    int tid = threadIdx.x;            // 256
    int s = code / 30, bk = (code / 3) % 10, ds = code % 3;
    int g = gen_ids[0];
    for (int f = tid; f < FFP; f += 256)
        g_feat[(size_t)code * FFP + f] =
            g_ftab[(size_t)s * FFP + f] + g_ftab[(size_t)(2 + g) * FFP + f] +
            g_ftab[(size_t)(9 + bk) * FFP + f] + g_ftab[(size_t)(19 + ds) * FFP + f];
}

__global__ void fine_init(const float* __restrict__ ab1)
{
    int r = blockIdx.x * 256 + threadIdx.x;
    if (r < PPAD) g_fine[r] = ab1[0];
}

// ---------------- 9) final output ----------------
__global__ void final_out(float* __restrict__ out, const float* __restrict__ dummy)
{
    int i = blockIdx.x;
    int tid = threadIdx.x;            // 64
    if (tid == 0) out[i * (CANT + 1)] = dummy[0];
    if (tid < CANT) {
        int p = g_antpos[i * CANT + tid];
        bool valid = p < i;
        out[i * (CANT + 1) + 1 + tid] =
            valid ? (g_antsc[i * CANT + tid] + g_fine[i * CANT + tid] * 2.0f) : NEG9;
    }
}

// ---------------- launch ----------------
extern "C" void kernel_launch(void* const* d_in, const int* in_sizes, int n_in,
                              void* d_out, int out_size)
{
    const float* h          = (const float*)d_in[0];
    const int*   spans      = (const int*)  d_in[1];
    const int*   spk_ids    = (const int*)  d_in[2];
    const int*   gen_ids    = (const int*)  d_in[3];
    const int*   sent_map   = (const int*)  d_in[4];
    const float* w_head     = (const float*)d_in[5];
    const float* b_head     = (const float*)d_in[6];
    const float* width_emb  = (const float*)d_in[7];
    const float* width_prior= (const float*)d_in[8];
    const float* speaker_emb= (const float*)d_in[9];
    const float* segment_emb= (const float*)d_in[10];
    const float* genre_emb  = (const float*)d_in[11];
    const float* dist_emb   = (const float*)d_in[12];
    const float* mention_w0 = (const float*)d_in[13];
    const float* mention_b0 = (const float*)d_in[14];
    const float* mention_w1 = (const float*)d_in[15];
    const float* mention_b1 = (const float*)d_in[16];
    const float* width_w0   = (const float*)d_in[17];
    const float* width_b0   = (const float*)d_in[18];
    const float* width_w1   = (const float*)d_in[19];
    const float* width_b1   = (const float*)d_in[20];
    const float* c2_w       = (const float*)d_in[21];
    const float* c2_b       = (const float*)d_in[22];
    const float* ant_w0     = (const float*)d_in[23];
    const float* ant_b0     = (const float*)d_in[24];
    const float* ant_w1     = (const float*)d_in[25];
    const float* ant_b1     = (const float*)d_in[26];
    const float* dummy_bias = (const float*)d_in[27];
    float* out = (float*)d_out;

    // weight conversions
    {
        size_t n1 = (size_t)KPAD * FFP;
        conv_w0<<<(unsigned)((n1 + 255) / 256), 256>>>(mention_w0);
        size_t n3 = 3 * n1;
        conv_aw0<<<(unsigned)((n3 + 255) / 256), 256>>>(ant_w0);
    }

    span_prep<<<NSP, 128>>>(h, spans, w_head, b_head, width_emb);
    width_scores<<<MAXW, 256>>>(width_prior, width_w0, width_b0, width_w1, width_b1);
    m_init<<<(NSP + 255) / 256, 256>>>(mention_b1);

    // mention MLP (bf16 tensor cores, fused epilogue)
    hgemm<0><<<dim3(NCB, NSP / BM), 256>>>(mention_b0, mention_w1, NSP);
    mlp_reduce<<<(NSP + 255) / 256, 256>>>(0, NSP);

    topk_mentions<<<1, 1024>>>(spk_ids, sent_map);
    gather_topbase<<<KTOP, 256>>>();

    dim3 gs((MD + 127) / 128, (KTOP + 127) / 128);
    src_gemm<<<gs, 256>>>(c2_w, c2_b);

    dim3 gc((KTOP + 15) / 16, (KTOP + 15) / 16);
    cp_kernel<<<gc, dim3(16, 16)>>>();
    topc<<<KTOP, 128>>>();

    featproj<<<22, 256>>>(ant_w0, speaker_emb, genre_emb, dist_emb, segment_emb);
    featcomb<<<60, 256>>>(gen_ids);

    // UA = top_base @ W0a (z=0), UB = top_base @ W0b (z=1), single launch
    hgemm<2><<<dim3(NCB, 2, 2), 256>>>(nullptr, nullptr, KTOP);

    fine_init<<<PPAD / 256, 256>>>(ant_b1);

    // fine pairwise MLP (bf16 tensor cores, A built on the fly, fused epilogue)
    hgemm<1><<<dim3(NCB, PPAD / BM), 256>>>(ant_b0, ant_w1, PPAD);
    mlp_reduce<<<(PPAD + 255) / 256, 256>>>(1, PPAD);

    final_out<<<KTOP, 64>>>(out, dummy_bias);
}

// round 4
// speedup vs baseline: 9.0545x; 1.3630x over previous
#include <cuda_runtime.h>
#include <cuda_bf16.h>
#include <math.h>
#include <stdint.h>

#define NSP   8192
#define LEN   512
#define HD    768
#define MAXW  30
#define FFD   3000
#define MD    2324      // 3*768+20
#define KTOP  204
#define CANT  50
#define PROWS 10200     // KTOP*CANT
#define PPAD  10240
#define NEG9  (-1e9f)

#define KPAD  2336      // MD padded to multiple of 32
#define FFP   3072      // FFD padded to multiple of 128
#define C2N   2432      // MD padded to multiple of 128 (src gemm N)
#define NCB   24        // FFP/128
#define BM    128
#define BN    128
#define BKK   32
#define SECT  ((size_t)KPAD * FFP)

#define STAGES 3
#define A_PITCH 40
#define B_PITCH 136
#define A_BYTES (BM * A_PITCH * 2)        // 10240
#define B_BYTES (BKK * B_PITCH * 2)       // 8704
#define STAGE_BYTES (A_BYTES + B_BYTES)   // 18944
#define DSMEM (STAGES * STAGE_BYTES)      // 56832

// ---------------- scratch (static device globals; zero-initialized) ----------------
__device__ __nv_bfloat16  g_baseh[(size_t)NSP * KPAD];     // bf16 base, padded
__device__ __nv_bfloat16  g_w0h[(size_t)KPAD * FFP];       // mention_w0 bf16
__device__ __nv_bfloat16  g_aw0h[3 * (size_t)KPAD * FFP];  // ant_w0 sections a,b,c
__device__ __nv_bfloat16  g_c2h[(size_t)KPAD * C2N];       // c2_w bf16 padded
__device__ __nv_bfloat16  g_pairh[(size_t)PPAD * KPAD];    // pairwise product rows
__device__ int   g_w[NSP];
__device__ int   g_s[NSP];
__device__ float g_m[NSP];
__device__ float g_wpart[MAXW * 6];
__device__ int   g_topidx[KTOP];
__device__ float g_topm[KTOP];
__device__ int   g_topspk[KTOP];
__device__ int   g_topseg[KTOP];
__device__ float g_topbase[(size_t)KTOP * MD];
__device__ __nv_bfloat16 g_topbaseh[(size_t)256 * KPAD];   // rows 204..255 stay 0
__device__ float g_src[(size_t)KTOP * MD];
__device__ float g_cp[KTOP * KTOP];
__device__ float g_antsc[KTOP * CANT];
__device__ int   g_antpos[KTOP * CANT];
__device__ float g_uabA[(size_t)KTOP * FFP];
__device__ float g_uabB[(size_t)KTOP * FFP];
__device__ float g_ftab[22 * FFP];
__device__ float g_feat[60 * FFP];
__device__ float g_fine[PPAD];
__device__ float g_part[(size_t)PPAD * NCB];

// orderable key: primary = value descending, secondary = index ascending
__device__ __forceinline__ unsigned long long make_key(float v, unsigned idx) {
    unsigned u = __float_as_uint(v);
    u = (u & 0x80000000u) ? ~u : (u | 0x80000000u);
    return ((unsigned long long)u << 32) | (unsigned)(0xFFFFFFFFu - idx);
}
__device__ __forceinline__ int key_idx(unsigned long long k) {
    return (int)(0xFFFFFFFFu - (unsigned)(k & 0xFFFFFFFFu));
}

// ---------------- PTX helpers ----------------
__device__ __forceinline__ void cp_async16(void* s, const void* g) {
    uint32_t sa = (uint32_t)__cvta_generic_to_shared(s);
    asm volatile("cp.async.cg.shared.global [%0], [%1], 16;" :: "r"(sa), "l"(g));
}
__device__ __forceinline__ void cp_commit() { asm volatile("cp.async.commit_group;"); }
template<int N> __device__ __forceinline__ void cp_wait() {
    asm volatile("cp.async.wait_group %0;" :: "n"(N));
}
__device__ __forceinline__ void ldsm_x4(uint32_t* r, uint32_t addr) {
    asm volatile("ldmatrix.sync.aligned.m8n8.x4.shared.b16 {%0,%1,%2,%3}, [%4];"
                 : "=r"(r[0]), "=r"(r[1]), "=r"(r[2]), "=r"(r[3]) : "r"(addr));
}
__device__ __forceinline__ void ldsm_x4_t(uint32_t* r, uint32_t addr) {
    asm volatile("ldmatrix.sync.aligned.m8n8.x4.trans.shared.b16 {%0,%1,%2,%3}, [%4];"
                 : "=r"(r[0]), "=r"(r[1]), "=r"(r[2]), "=r"(r[3]) : "r"(addr));
}
__device__ __forceinline__ void mma_bf16(float* c, const uint32_t* a, uint32_t b0, uint32_t b1) {
    asm volatile("mma.sync.aligned.m16n8k16.row.col.f32.bf16.bf16.f32 "
                 "{%0,%1,%2,%3}, {%4,%5,%6,%7}, {%8,%9}, {%0,%1,%2,%3};"
                 : "+f"(c[0]), "+f"(c[1]), "+f"(c[2]), "+f"(c[3])
                 : "r"(a[0]), "r"(a[1]), "r"(a[2]), "r"(a[3]), "r"(b0), "r"(b1));
}

// ---------------- weight conversions fp32 -> padded bf16 ----------------
__global__ void conv_w0(const float* __restrict__ w0)
{
    size_t idx = (size_t)blockIdx.x * 256 + threadIdx.x;
    if (idx >= (size_t)KPAD * FFP) return;
    int d = (int)(idx / FFP), f = (int)(idx % FFP);
    float v = (d < MD && f < FFD) ? w0[(size_t)d * FFD + f] : 0.f;
    g_w0h[idx] = __float2bfloat16(v);
}
__global__ void conv_aw0(const float* __restrict__ w0)
{
    size_t idx = (size_t)blockIdx.x * 256 + threadIdx.x;
    if (idx >= 3 * (size_t)KPAD * FFP) return;
    size_t per = (size_t)KPAD * FFP;
    int s = (int)(idx / per);
    size_t rem = idx % per;
    int d = (int)(rem / FFP), f = (int)(rem % FFP);
    float v = (d < MD && f < FFD) ? w0[(size_t)(s * MD + d) * FFD + f] : 0.f;
    g_aw0h[idx] = __float2bfloat16(v);
}
__global__ void conv_c2(const float* __restrict__ c2w)
{
    size_t idx = (size_t)blockIdx.x * 256 + threadIdx.x;
    if (idx >= (size_t)KPAD * C2N) return;
    int d = (int)(idx / C2N), f = (int)(idx % C2N);
    float v = (d < MD && f < MD) ? c2w[(size_t)d * MD + f] : 0.f;
    g_c2h[idx] = __float2bfloat16(v);
}

// ---------------- 1) span extraction + head attention + base embedding ----------------
__global__ void span_prep(const float* __restrict__ h, const int* __restrict__ spans,
                          const float* __restrict__ w_head, const float* __restrict__ b_head,
                          const float* __restrict__ width_emb)
{
    int n = blockIdx.x;
    int tid = threadIdx.x;            // 128 threads
    int lane = tid & 31, warp = tid >> 5;
    __shared__ float sc[32];
    __shared__ float wts[32];
    __shared__ int shr[3];
    if (tid == 0) {
        int s = spans[2 * n], e = spans[2 * n + 1];
        s = min(max(s, 0), LEN - 1);
        e = min(max(e, 0), LEN - 1);
        int w = e - s + 1;
        if (w < 1) w = 1;
        if (w > MAXW) w = MAXW;
        shr[0] = s; shr[1] = e; shr[2] = w;
        g_s[n] = s; g_w[n] = w;
    }
    __syncthreads();
    int s = shr[0], e = shr[1], w = shr[2];

    for (int wp = warp; wp < w; wp += 4) {
        const float* row = h + (size_t)(s + wp) * HD;
        float acc = 0.f;
        for (int c = lane; c < HD; c += 32) acc += row[c] * w_head[c];
        #pragma unroll
        for (int o = 16; o > 0; o >>= 1) acc += __shfl_down_sync(0xffffffffu, acc, o);
        if (lane == 0) sc[wp] = acc + b_head[0];
    }
    __syncthreads();
    if (warp == 0) {
        float v = (lane < w) ? sc[lane] : -1e30f;
        float mx = v;
        #pragma unroll
        for (int o = 16; o > 0; o >>= 1) mx = fmaxf(mx, __shfl_xor_sync(0xffffffffu, mx, o));
        float p = (lane < w) ? expf(v - mx) : 0.f;
        float sm = p;
        #pragma unroll
        for (int o = 16; o > 0; o >>= 1) sm += __shfl_xor_sync(0xffffffffu, sm, o);
        wts[lane] = p / sm;
    }
    __syncthreads();

    size_t bh = (size_t)n * KPAD;
    const float* hs = h + (size_t)s * HD;
    const float* he = h + (size_t)e * HD;
    for (int c = tid; c < HD; c += 128) {
        float acc = 0.f;
        for (int wp = 0; wp < w; wp++) acc += wts[wp] * h[(size_t)(s + wp) * HD + c];
        g_baseh[bh + c]          = __float2bfloat16(hs[c]);
        g_baseh[bh + HD + c]     = __float2bfloat16(he[c]);
        g_baseh[bh + 2 * HD + c] = __float2bfloat16(acc);
    }
    if (tid < 20)
        g_baseh[bh + 3 * HD + tid] = __float2bfloat16(width_emb[(w - 1) * 20 + tid]);
}

// ---------------- 2) width-prior MLP (30 widths x 6 f-segments) ----------------
__global__ void width_scores(const float* __restrict__ wprior, const float* __restrict__ w0,
                             const float* __restrict__ b0, const float* __restrict__ w1)
{
    int w = blockIdx.x, seg = blockIdx.y;
    int tid = threadIdx.x;            // 256
    __shared__ float wv[20];
    __shared__ float red[256];
    if (tid < 20) wv[tid] = wprior[w * 20 + tid];
    __syncthreads();
    float acc = 0.f;
    int f0 = seg * 512;
    int f1 = min(f0 + 512, FFD);
    for (int f = f0 + tid; f < f1; f += 256) {
        float d = b0[f];
        #pragma unroll
        for (int k = 0; k < 20; k++) d += wv[k] * w0[k * FFD + f];
        acc += fmaxf(d, 0.f) * w1[f];
    }
    red[tid] = acc;
    __syncthreads();
    for (int o = 128; o > 0; o >>= 1) { if (tid < o) red[tid] += red[tid + o]; __syncthreads(); }
    if (tid == 0) g_wpart[w * 6 + seg] = red[0];
}

__global__ void m_init(const float* __restrict__ mb1, const float* __restrict__ wb1)
{
    int n = blockIdx.x * 256 + threadIdx.x;
    if (n >= NSP) return;
    int w = g_w[n] - 1;
    float acc = mb1[0] + wb1[0];
    #pragma unroll
    for (int c = 0; c < 6; c++) acc += g_wpart[w * 6 + c];
    g_m[n] = acc;
}

// ---------------- 3) bf16 tensor-core GEMM with cp.async 3-stage pipeline ----------------
// EPI 0: fused mention epilogue -> g_part    (A=g_baseh,  B=g_w0h)
// EPI 1: fused fine epilogue    -> g_part    (A=g_pairh,  B=g_aw0h sec2, + uA/uB/feat)
// EPI 2: raw C (+optional bias) -> outC      (A=g_topbaseh, B & outC per launch)
template<int EPI>
__global__ __launch_bounds__(256, 1) void hgemm2(
    const __nv_bfloat16* __restrict__ A,
    const __nv_bfloat16* __restrict__ Bg, int ldb,
    const float* __restrict__ b0v, const float* __restrict__ w1v,
    float* __restrict__ outC, int ldc, int R, int maxC)
{
    extern __shared__ char smem[];
    __shared__ float rowsum[BM];
    __shared__ int sRi[BM], sRp[BM], sRc[BM];

    int tid = threadIdx.x;
    int lane = tid & 31, warp = tid >> 5;
    int wm = warp >> 2, wn = warp & 3;
    int row0 = blockIdx.y * BM, col0 = blockIdx.x * BN;

    if (tid < BM) {
        rowsum[tid] = 0.f;
        if (EPI == 1) {
            int r = row0 + tid;
            int i = r / CANT; if (i > KTOP - 1) i = KTOP - 1;
            int p = (r < PROWS) ? g_antpos[r] : 0;
            sRi[tid] = i; sRp[tid] = p;
            int same = (g_topspk[i] == g_topspk[p]) ? 1 : 0;
            int off = i - p; if (off < 0) off = 0;
            int bk = off >= 64 ? 9 : off >= 32 ? 8 : off >= 16 ? 7 : off >= 8 ? 6 : off >= 5 ? 5 : off;
            int ds = g_topseg[i] - g_topseg[p]; ds = ds < 0 ? 0 : (ds > 2 ? 2 : ds);
            sRc[tid] = (same * 10 + bk) * 3 + ds;
        }
    }
    __syncthreads();

    float acc[4][4][4];
    #pragma unroll
    for (int a = 0; a < 4; a++)
        #pragma unroll
        for (int b = 0; b < 4; b++)
            #pragma unroll
            for (int c = 0; c < 4; c++) acc[a][b][c] = 0.f;

    const int KT = KPAD / BKK;    // 73

    auto issue = [&](int kt) {
        int k0 = kt * BKK;
        char* sa = smem + (size_t)(kt % STAGES) * STAGE_BYTES;
        char* sb = sa + A_BYTES;
        #pragma unroll
        for (int v = 0; v < 2; v++) {
            int idx = tid + v * 256;
            int arow = idx >> 2, aseg = idx & 3;
            cp_async16(sa + (size_t)(arow * A_PITCH + aseg * 8) * 2,
                       A + (size_t)(row0 + arow) * KPAD + k0 + aseg * 8);
            int brow = idx >> 4, bseg = idx & 15;
            cp_async16(sb + (size_t)(brow * B_PITCH + bseg * 8) * 2,
                       Bg + (size_t)(k0 + brow) * ldb + col0 + bseg * 8);
        }
    };

    #pragma unroll
    for (int s = 0; s < STAGES - 1; s++) { issue(s); cp_commit(); }

    for (int kt = 0; kt < KT; kt++) {
        cp_wait<STAGES - 2>();
        __syncthreads();
        if (kt + STAGES - 1 < KT) issue(kt + STAGES - 1);
        cp_commit();

        int cur = kt % STAGES;
        const __nv_bfloat16 (*As)[A_PITCH] =
            (const __nv_bfloat16 (*)[A_PITCH])(smem + (size_t)cur * STAGE_BYTES);
        const __nv_bfloat16 (*Bs)[B_PITCH] =
            (const __nv_bfloat16 (*)[B_PITCH])(smem + (size_t)cur * STAGE_BYTES + A_BYTES);

        #pragma unroll
        for (int kk = 0; kk < BKK; kk += 16) {
            uint32_t af[4][4];
            #pragma unroll
            for (int mf = 0; mf < 4; mf++) {
                uint32_t addr = (uint32_t)__cvta_generic_to_shared(
                    &As[wm * 64 + mf * 16 + (lane & 15)][kk + ((lane >> 4) << 3)]);
                ldsm_x4(af[mf], addr);
            }
            uint32_t bfr[2][4];
            #pragma unroll
            for (int g = 0; g < 2; g++) {
                int krow = kk + (lane & 7) + ((lane & 8) ? 8 : 0);
                int bcol = wn * 32 + g * 16 + ((lane & 16) ? 8 : 0);
                uint32_t addr = (uint32_t)__cvta_generic_to_shared(&Bs[krow][bcol]);
                ldsm_x4_t(bfr[g], addr);
            }
            #pragma unroll
            for (int mf = 0; mf < 4; mf++)
                #pragma unroll
                for (int nf = 0; nf < 4; nf++)
                    mma_bf16(acc[mf][nf], af[mf], bfr[nf >> 1][(nf & 1) * 2],
                             bfr[nf >> 1][(nf & 1) * 2 + 1]);
        }
    }

    if (EPI == 2) {
        #pragma unroll
        for (int mf = 0; mf < 4; mf++)
            #pragma unroll
            for (int rr = 0; rr < 2; rr++) {
                int r = row0 + wm * 64 + mf * 16 + (lane >> 2) + rr * 8;
                if (r >= R) continue;
                #pragma unroll
                for (int nf = 0; nf < 4; nf++) {
                    int f = col0 + wn * 32 + nf * 8 + (lane & 3) * 2;
                    #pragma unroll
                    for (int c = 0; c < 2; c++) {
                        if (f + c < maxC) {
                            float v = acc[mf][nf][rr * 2 + c];
                            if (b0v) v += b0v[f + c];
                            outC[(size_t)r * ldc + f + c] = v;
                        }
                    }
                }
            }
        return;
    }

    // fused epilogue: relu(acc + bias terms) * w1, reduce over block columns
    #pragma unroll
    for (int mf = 0; mf < 4; mf++)
        #pragma unroll
        for (int rr = 0; rr < 2; rr++) {
            int lrow = wm * 64 + mf * 16 + (lane >> 2) + rr * 8;
            const float* uA = nullptr; const float* uB = nullptr; const float* uF = nullptr;
            if (EPI == 1) {
                uA = g_uabA + (size_t)sRi[lrow] * FFP;
                uB = g_uabB + (size_t)sRp[lrow] * FFP;
                uF = g_feat + (size_t)sRc[lrow] * FFP;
            }
            float part = 0.f;
            #pragma unroll
            for (int nf = 0; nf < 4; nf++)
                #pragma unroll
                for (int c = 0; c < 2; c++) {
                    int f = col0 + wn * 32 + nf * 8 + (lane & 3) * 2 + c;
                    float v = acc[mf][nf][rr * 2 + c];
                    if (f < FFD) v += b0v[f];
                    if (EPI == 1) v += uA[f] + uB[f] + uF[f];
                    float w1f = (f < FFD) ? w1v[f] : 0.f;
                    part += fmaxf(v, 0.f) * w1f;
                }
            atomicAdd(&rowsum[lrow], part);
        }
    __syncthreads();
    if (tid < BM) {
        int r = row0 + tid;
        if (r < R) g_part[(size_t)r * NCB + blockIdx.x] = rowsum[tid];
    }
}

__global__ void mlp_reduce(const float* __restrict__ initv, int which, int R)
{
    int r = blockIdx.x * 256 + threadIdx.x;
    if (r >= R) return;
    float acc = 0.f;
    #pragma unroll
    for (int c = 0; c < NCB; c++) acc += g_part[(size_t)r * NCB + c];
    if (which) g_fine[r] = initv[0] + acc;
    else       g_m[r] += acc;
}

// ---------------- 4) top-K mentions: 64-bit radix select in smem ----------------
__global__ void topk_mentions(const int* __restrict__ spk, const int* __restrict__ sent)
{
    extern __shared__ unsigned long long skeys[];   // NSP keys (64 KB)
    __shared__ int hist[256];
    __shared__ int tix[256];
    __shared__ unsigned long long s_pfx;
    __shared__ int s_tgt, s_cnt;
    int tid = threadIdx.x;            // 1024
    for (int i = tid; i < NSP; i += 1024) skeys[i] = make_key(g_m[i], (unsigned)i);
    if (tid == 0) { s_tgt = KTOP; s_pfx = 0ull; s_cnt = 0; }
    __syncthreads();

    for (int byte = 7; byte >= 0; byte--) {
        int shift = byte * 8;
        if (tid < 256) hist[tid] = 0;
        __syncthreads();
        unsigned long long pfx = s_pfx;
        for (int i = tid; i < NSP; i += 1024) {
            unsigned long long k = skeys[i];
            bool match = (byte == 7) || ((k >> (shift + 8)) == (pfx >> (shift + 8)));
            if (match) atomicAdd(&hist[(int)((k >> shift) & 255)], 1);
        }
        __syncthreads();
        if (tid == 0) {
            int cum = 0, v = 255;
            for (; v > 0; v--) { if (cum + hist[v] >= s_tgt) break; cum += hist[v]; }
            s_tgt -= cum;
            s_pfx = pfx | ((unsigned long long)(unsigned)v << shift);
        }
        __syncthreads();
    }
    unsigned long long thr = s_pfx;   // exact KTOP-th largest key (keys unique)
    for (int i = tid; i < NSP; i += 1024) {
        if (skeys[i] >= thr) {
            int pos = atomicAdd(&s_cnt, 1);
            if (pos < 256) tix[pos] = key_idx(skeys[i]);
        }
    }
    __syncthreads();
    for (int t = tid; t < 256; t += 1024) if (t >= KTOP) tix[t] = 0x7FFFFFFF;
    __syncthreads();
    // sort span indices ascending (document order)
    for (unsigned k = 2; k <= 256; k <<= 1)
        for (unsigned j = k >> 1; j > 0; j >>= 1) {
            for (unsigned t = tid; t < 256; t += 1024) {
                unsigned ixj = t ^ j;
                if (ixj > t) {
                    int a = tix[t], b = tix[ixj];
                    bool asc = ((t & k) == 0);
                    if (asc ? (a > b) : (a < b)) { tix[t] = b; tix[ixj] = a; }
                }
            }
            __syncthreads();
        }
    if (tid < KTOP) {
        int idx = tix[tid];
        g_topidx[tid] = idx;
        g_topm[tid]   = g_m[idx];
        int s = g_s[idx];
        g_topspk[tid] = spk[s];
        g_topseg[tid] = sent[s];
    }
}

__global__ void gather_topbase()
{
    int i = blockIdx.x;               // KTOP blocks
    const __nv_bfloat16* src = g_baseh + (size_t)g_topidx[i] * KPAD;
    float* dst = g_topbase + (size_t)i * MD;
    __nv_bfloat16* dsh = g_topbaseh + (size_t)i * KPAD;
    for (int d = threadIdx.x; d < MD; d += 256) {
        __nv_bfloat16 v = src[d];
        dst[d] = __bfloat162float(v);
        dsh[d] = v;
    }
}

// ---------------- 6) coarse pair scores ----------------
__global__ void cp_kernel()
{
    __shared__ float As[16][17];
    __shared__ float Bs[16][17];
    int tx = threadIdx.x, ty = threadIdx.y;
    int i0 = blockIdx.y * 16, j0 = blockIdx.x * 16;
    int i = i0 + ty, j = j0 + tx;
    float acc = 0.f;
    for (int k0 = 0; k0 < MD; k0 += 16) {
        int k = k0 + tx;
        As[ty][tx] = (i0 + ty < KTOP && k < MD) ? g_src[(size_t)(i0 + ty) * MD + k] : 0.f;
        Bs[ty][tx] = (j0 + ty < KTOP && k < MD) ? g_topbase[(size_t)(j0 + ty) * MD + k] : 0.f;
        __syncthreads();
        #pragma unroll
        for (int kk = 0; kk < 16; kk++) acc += As[ty][kk] * Bs[tx][kk];
        __syncthreads();
    }
    if (i < KTOP && j < KTOP) {
        float v = acc + g_topm[i] + g_topm[j];
        if (j >= i) v = NEG9;
        g_cp[i * KTOP + j] = v;
    }
}

// ---------------- 7) per-row top-C antecedents ----------------
__global__ void topc()
{
    int i = blockIdx.x;
    int tid = threadIdx.x;            // 128
    __shared__ unsigned long long keys[256];
    for (int t = tid; t < 256; t += 128)
        keys[t] = (t < KTOP) ? make_key(g_cp[i * KTOP + t], (unsigned)t) : 0ull;
    __syncthreads();
    for (unsigned k = 2; k <= 256; k <<= 1)
        for (unsigned j = k >> 1; j > 0; j >>= 1) {
            for (unsigned t = tid; t < 256; t += 128) {
                unsigned ixj = t ^ j;
                if (ixj > t) {
                    unsigned long long a = keys[t], b = keys[ixj];
                    bool desc = ((t & k) == 0);
                    if (desc ? (a < b) : (a > b)) { keys[t] = b; keys[ixj] = a; }
                }
            }
            __syncthreads();
        }
    if (tid < CANT) {
        int pos = key_idx(keys[tid]);
        g_antpos[i * CANT + tid] = pos;
        g_antsc[i * CANT + tid] = g_cp[i * KTOP + pos];
    }
}

// ---------------- 8) pairwise product rows (bf16) ----------------
__global__ void pack_prod()
{
    int r = blockIdx.x;               // PPAD
    int tid = threadIdx.x;            // 256
    int i = r / CANT; if (i > KTOP - 1) i = KTOP - 1;
    int p = (r < PROWS) ? g_antpos[r] : 0;
    const uint4* a = (const uint4*)(g_topbaseh + (size_t)i * KPAD);
    const uint4* b = (const uint4*)(g_topbaseh + (size_t)p * KPAD);
    uint4* o = (uint4*)(g_pairh + (size_t)r * KPAD);
    for (int v = tid; v < KPAD / 8; v += 256) {
        uint4 va = a[v], vb = b[v], vo;
        __nv_bfloat162* pa = (__nv_bfloat162*)&va;
        __nv_bfloat162* pb = (__nv_bfloat162*)&vb;
        __nv_bfloat162* po = (__nv_bfloat162*)&vo;
        #pragma unroll
        for (int q = 0; q < 4; q++) po[q] = __hmul2(pa[q], pb[q]);
        o[v] = vo;
    }
}

// ---------------- 9) feature table projections ----------------
__global__ void featproj(const float* __restrict__ aw0,
                         const float* __restrict__ spk_emb, const float* __restrict__ gen_emb,
                         const float* __restrict__ dist_emb, const float* __restrict__ seg_emb)
{
    int row = blockIdx.x;             // 22
    int tid = threadIdx.x;            // 256
    const float* emb; int off;
    if (row < 2)       { emb = spk_emb  + row * 20;        off = 0; }
    else if (row < 9)  { emb = gen_emb  + (row - 2) * 20;  off = 20; }
    else if (row < 19) { emb = dist_emb + (row - 9) * 20;  off = 40; }
    else               { emb = seg_emb  + (row - 19) * 20; off = 60; }
    __shared__ float ev[20];
    if (tid < 20) ev[tid] = emb[tid];
    __syncthreads();
    for (int f = tid; f < FFP; f += 256) {
        float acc = 0.f;
        if (f < FFD) {
            #pragma unroll
            for (int k = 0; k < 20; k++)
                acc += ev[k] * aw0[(size_t)(3 * MD + off + k) * FFD + f];
        }
        g_ftab[(size_t)row * FFP + f] = acc;
    }
}

__global__ void featcomb(const int* __restrict__ gen_ids)
{
    int code = blockIdx.x;            // 60
    int tid = threadIdx.x;            // 256
    int s = code / 30, bk = (code / 3) % 10, ds = code % 3;
    int g = gen_ids[0];
    for (int f = tid; f < FFP; f += 256)
        g_feat[(size_t)code * FFP + f] =
            g_ftab[(size_t)s * FFP + f] + g_ftab[(size_t)(2 + g) * FFP + f] +
            g_ftab[(size_t)(9 + bk) * FFP + f] + g_ftab[(size_t)(19 + ds) * FFP + f];
}

// ---------------- 10) final output ----------------
__global__ void final_out(float* __restrict__ out, const float* __restrict__ dummy)
{
    int i = blockIdx.x;
    int tid = threadIdx.x;            // 64
    if (tid == 0) out[i * (CANT + 1)] = dummy[0];
    if (tid < CANT) {
        int p = g_antpos[i * CANT + tid];
        bool valid = p < i;
        out[i * (CANT + 1) + 1 + tid] =
            valid ? (g_antsc[i * CANT + tid] + g_fine[i * CANT + tid] * 2.0f) : NEG9;
    }
}

// ---------------- launch ----------------
extern "C" void kernel_launch(void* const* d_in, const int* in_sizes, int n_in,
                              void* d_out, int out_size)
{
    const float* h          = (const float*)d_in[0];
    const int*   spans      = (const int*)  d_in[1];
    const int*   spk_ids    = (const int*)  d_in[2];
    const int*   gen_ids    = (const int*)  d_in[3];
    const int*   sent_map   = (const int*)  d_in[4];
    const float* w_head     = (const float*)d_in[5];
    const float* b_head     = (const float*)d_in[6];
    const float* width_emb  = (const float*)d_in[7];
    const float* width_prior= (const float*)d_in[8];
    const float* speaker_emb= (const float*)d_in[9];
    const float* segment_emb= (const float*)d_in[10];
    const float* genre_emb  = (const float*)d_in[11];
    const float* dist_emb   = (const float*)d_in[12];
    const float* mention_w0 = (const float*)d_in[13];
    const float* mention_b0 = (const float*)d_in[14];
    const float* mention_w1 = (const float*)d_in[15];
    const float* mention_b1 = (const float*)d_in[16];
    const float* width_w0   = (const float*)d_in[17];
    const float* width_b0   = (const float*)d_in[18];
    const float* width_w1   = (const float*)d_in[19];
    const float* width_b1   = (const float*)d_in[20];
    const float* c2_w       = (const float*)d_in[21];
    const float* c2_b       = (const float*)d_in[22];
    const float* ant_w0     = (const float*)d_in[23];
    const float* ant_b0     = (const float*)d_in[24];
    const float* ant_w1     = (const float*)d_in[25];
    const float* ant_b1     = (const float*)d_in[26];
    const float* dummy_bias = (const float*)d_in[27];
    float* out = (float*)d_out;

    // opt-in smem limits (host-side attribute set; executes at capture time, no allocation)
    cudaFuncSetAttribute(hgemm2<0>, cudaFuncAttributeMaxDynamicSharedMemorySize, DSMEM);
    cudaFuncSetAttribute(hgemm2<1>, cudaFuncAttributeMaxDynamicSharedMemorySize, DSMEM);
    cudaFuncSetAttribute(hgemm2<2>, cudaFuncAttributeMaxDynamicSharedMemorySize, DSMEM);
    cudaFuncSetAttribute(topk_mentions, cudaFuncAttributeMaxDynamicSharedMemorySize, NSP * 8);

    // device-global addresses for GEMM operands
    void *pBaseh, *pW0h, *pAw0h, *pC2h, *pPairh, *pTopbh, *pUA, *pUB, *pSrc;
    cudaGetSymbolAddress(&pBaseh, g_baseh);
    cudaGetSymbolAddress(&pW0h,   g_w0h);
    cudaGetSymbolAddress(&pAw0h,  g_aw0h);
    cudaGetSymbolAddress(&pC2h,   g_c2h);
    cudaGetSymbolAddress(&pPairh, g_pairh);
    cudaGetSymbolAddress(&pTopbh, g_topbaseh);
    cudaGetSymbolAddress(&pUA,    g_uabA);
    cudaGetSymbolAddress(&pUB,    g_uabB);
    cudaGetSymbolAddress(&pSrc,   g_src);
    const __nv_bfloat16* baseh = (const __nv_bfloat16*)pBaseh;
    const __nv_bfloat16* w0h   = (const __nv_bfloat16*)pW0h;
    const __nv_bfloat16* aw0h  = (const __nv_bfloat16*)pAw0h;
    const __nv_bfloat16* c2h   = (const __nv_bfloat16*)pC2h;
    const __nv_bfloat16* pairh = (const __nv_bfloat16*)pPairh;
    const __nv_bfloat16* topbh = (const __nv_bfloat16*)pTopbh;

    // weight conversions
    {
        size_t n1 = (size_t)KPAD * FFP;
        conv_w0<<<(unsigned)((n1 + 255) / 256), 256>>>(mention_w0);
        conv_aw0<<<(unsigned)((3 * n1 + 255) / 256), 256>>>(ant_w0);
        size_t n2 = (size_t)KPAD * C2N;
        conv_c2<<<(unsigned)((n2 + 255) / 256), 256>>>(c2_w);
    }

    span_prep<<<NSP, 128>>>(h, spans, w_head, b_head, width_emb);
    width_scores<<<dim3(MAXW, 6), 256>>>(width_prior, width_w0, width_b0, width_w1);
    m_init<<<(NSP + 255) / 256, 256>>>(mention_b1, width_b1);

    // mention MLP
    hgemm2<0><<<dim3(NCB, NSP / BM), 256, DSMEM>>>(
        baseh, w0h, FFP, mention_b0, mention_w1, nullptr, 0, NSP, FFP);
    mlp_reduce<<<(NSP + 255) / 256, 256>>>(nullptr, 0, NSP);

    topk_mentions<<<1, 1024, NSP * 8>>>(spk_ids, sent_map);
    gather_topbase<<<KTOP, 256>>>();

    // src = top_base @ c2_w + c2_b  (bf16 tensor cores)
    hgemm2<2><<<dim3(C2N / BN, 2), 256, DSMEM>>>(
        topbh, c2h, C2N, c2_b, nullptr, (float*)pSrc, MD, KTOP, MD);

    dim3 gc((KTOP + 15) / 16, (KTOP + 15) / 16);
    cp_kernel<<<gc, dim3(16, 16)>>>();
    topc<<<KTOP, 128>>>();

    featproj<<<22, 256>>>(ant_w0, speaker_emb, genre_emb, dist_emb, segment_emb);
    featcomb<<<60, 256>>>(gen_ids);

    // UA = top_base @ W0a, UB = top_base @ W0b
    hgemm2<2><<<dim3(NCB, 2), 256, DSMEM>>>(
        topbh, aw0h, FFP, nullptr, nullptr, (float*)pUA, FFP, KTOP, FFP);
    hgemm2<2><<<dim3(NCB, 2), 256, DSMEM>>>(
        topbh, aw0h + SECT, FFP, nullptr, nullptr, (float*)pUB, FFP, KTOP, FFP);

    pack_prod<<<PPAD, 256>>>();

    // fine pairwise MLP
    hgemm2<1><<<dim3(NCB, PPAD / BM), 256, DSMEM>>>(
        pairh, aw0h + 2 * SECT, FFP, ant_b0, ant_w1, nullptr, 0, PPAD, FFP);
    mlp_reduce<<<(PPAD + 255) / 256, 256>>>(ant_b1, 1, PPAD);

    final_out<<<KTOP, 64>>>(out, dummy_bias);
}

// round 6
// speedup vs baseline: 11.6917x; 1.2913x over previous
#include <cuda_runtime.h>
#include <cuda_bf16.h>
#include <math.h>
#include <stdint.h>

#define NSP   8192
#define LEN   512
#define HD    768
#define MAXW  30
#define FFD   3000
#define MD    2324      // 3*768+20
#define KTOP  204
#define CANT  50
#define PROWS 10200     // KTOP*CANT
#define PPAD  10240
#define NEG9  (-1e9f)

#define KPAD  2336      // MD padded to multiple of 32
#define FFP   3072      // FFD padded to multiple of 128
#define C2N   2432      // MD padded to multiple of 128 (src gemm N)
#define NCB   24        // FFP/128
#define BM    128
#define BN    128
#define BKK   32
#define SECT  ((size_t)KPAD * FFP)

#define STAGES 4
#define A_PITCH 40
#define B_PITCH 136
#define A_BYTES (BM * A_PITCH * 2)        // 10240
#define B_BYTES (BKK * B_PITCH * 2)       // 8704
#define STAGE_BYTES (A_BYTES + B_BYTES)   // 18944
#define DSMEM (STAGES * STAGE_BYTES)      // 75776

// ---------------- scratch (static device globals; zero-initialized) ----------------
__device__ __nv_bfloat16  g_baseh[(size_t)NSP * KPAD];     // bf16 base, padded
__device__ __nv_bfloat16  g_w0h[(size_t)KPAD * FFP];       // mention_w0 bf16
__device__ __nv_bfloat16  g_aw0h[3 * (size_t)KPAD * FFP];  // ant_w0 sections a,b,c
__device__ __nv_bfloat16  g_c2h[(size_t)KPAD * C2N];       // c2_w bf16 padded
__device__ __nv_bfloat16  g_pairh[(size_t)PPAD * KPAD];    // pairwise product rows
__device__ float g_tok[LEN];
__device__ int   g_w[NSP];
__device__ int   g_s[NSP];
__device__ float g_m[NSP];
__device__ float g_wpart[MAXW * 6];
__device__ int   g_topidx[KTOP];
__device__ float g_topm[KTOP];
__device__ int   g_topspk[KTOP];
__device__ int   g_topseg[KTOP];
__device__ float g_topbase[(size_t)KTOP * MD];
__device__ __nv_bfloat16 g_topbaseh[(size_t)256 * KPAD];   // rows 204..255 stay 0
__device__ float g_src[(size_t)KTOP * MD];
__device__ float g_cp[KTOP * KTOP];
__device__ float g_antsc[KTOP * CANT];
__device__ int   g_antpos[KTOP * CANT];
__device__ float g_uabA[(size_t)KTOP * FFP];
__device__ float g_uabB[(size_t)KTOP * FFP];
__device__ float g_ftab[22 * FFP];
__device__ float g_feat[60 * FFP];
__device__ float g_fine[PPAD];
__device__ float g_part[(size_t)PPAD * NCB];

// orderable key: primary = value descending, secondary = index ascending
__device__ __forceinline__ unsigned long long make_key(float v, unsigned idx) {
    unsigned u = __float_as_uint(v);
    u = (u & 0x80000000u) ? ~u : (u | 0x80000000u);
    return ((unsigned long long)u << 32) | (unsigned)(0xFFFFFFFFu - idx);
}
__device__ __forceinline__ int key_idx(unsigned long long k) {
    return (int)(0xFFFFFFFFu - (unsigned)(k & 0xFFFFFFFFu));
}

// ---------------- PTX helpers ----------------
__device__ __forceinline__ void cp_async16(void* s, const void* g) {
    uint32_t sa = (uint32_t)__cvta_generic_to_shared(s);
    asm volatile("cp.async.cg.shared.global [%0], [%1], 16;" :: "r"(sa), "l"(g));
}
__device__ __forceinline__ void cp_commit() { asm volatile("cp.async.commit_group;"); }
template<int N> __device__ __forceinline__ void cp_wait() {
    asm volatile("cp.async.wait_group %0;" :: "n"(N));
}
__device__ __forceinline__ void ldsm_x4(uint32_t* r, uint32_t addr) {
    asm volatile("ldmatrix.sync.aligned.m8n8.x4.shared.b16 {%0,%1,%2,%3}, [%4];"
                 : "=r"(r[0]), "=r"(r[1]), "=r"(r[2]), "=r"(r[3]) : "r"(addr));
}
__device__ __forceinline__ void ldsm_x4_t(uint32_t* r, uint32_t addr) {
    asm volatile("ldmatrix.sync.aligned.m8n8.x4.trans.shared.b16 {%0,%1,%2,%3}, [%4];"
                 : "=r"(r[0]), "=r"(r[1]), "=r"(r[2]), "=r"(r[3]) : "r"(addr));
}
__device__ __forceinline__ void mma_bf16(float* c, const uint32_t* a, uint32_t b0, uint32_t b1) {
    asm volatile("mma.sync.aligned.m16n8k16.row.col.f32.bf16.bf16.f32 "
                 "{%0,%1,%2,%3}, {%4,%5,%6,%7}, {%8,%9}, {%0,%1,%2,%3};"
                 : "+f"(c[0]), "+f"(c[1]), "+f"(c[2]), "+f"(c[3])
                 : "r"(a[0]), "r"(a[1]), "r"(a[2]), "r"(a[3]), "r"(b0), "r"(b1));
}

// ---------------- weight conversions fp32 -> padded bf16 ----------------
__global__ void conv_w0(const float* __restrict__ w0)
{
    size_t idx = (size_t)blockIdx.x * 256 + threadIdx.x;
    if (idx >= (size_t)KPAD * FFP) return;
    int d = (int)(idx / FFP), f = (int)(idx % FFP);
    float v = (d < MD && f < FFD) ? w0[(size_t)d * FFD + f] : 0.f;
    g_w0h[idx] = __float2bfloat16(v);
}
__global__ void conv_aw0(const float* __restrict__ w0)
{
    size_t idx = (size_t)blockIdx.x * 256 + threadIdx.x;
    if (idx >= 3 * (size_t)KPAD * FFP) return;
    size_t per = (size_t)KPAD * FFP;
    int s = (int)(idx / per);
    size_t rem = idx % per;
    int d = (int)(rem / FFP), f = (int)(rem % FFP);
    float v = (d < MD && f < FFD) ? w0[(size_t)(s * MD + d) * FFD + f] : 0.f;
    g_aw0h[idx] = __float2bfloat16(v);
}
__global__ void conv_c2(const float* __restrict__ c2w)
{
    size_t idx = (size_t)blockIdx.x * 256 + threadIdx.x;
    if (idx >= (size_t)KPAD * C2N) return;
    int d = (int)(idx / C2N), f = (int)(idx % C2N);
    float v = (d < MD && f < MD) ? c2w[(size_t)d * MD + f] : 0.f;
    g_c2h[idx] = __float2bfloat16(v);
}

// ---------------- per-token head scores ----------------
__global__ void tok_score(const float* __restrict__ h, const float* __restrict__ w_head,
                          const float* __restrict__ b_head)
{
    int t = blockIdx.x * 32 + (threadIdx.x >> 5);
    int lane = threadIdx.x & 31;
    if (t >= LEN) return;
    const float* row = h + (size_t)t * HD;
    float acc = 0.f;
    for (int c = lane; c < HD; c += 32) acc += row[c] * w_head[c];
    #pragma unroll
    for (int o = 16; o > 0; o >>= 1) acc += __shfl_down_sync(0xffffffffu, acc, o);
    if (lane == 0) g_tok[t] = acc + b_head[0];
}

// ---------------- span extraction + head attention + base embedding ----------------
__global__ void span_prep(const float* __restrict__ h, const int* __restrict__ spans,
                          const float* __restrict__ width_emb)
{
    int n = blockIdx.x;
    int tid = threadIdx.x;            // 128 threads
    int lane = tid & 31, warp = tid >> 5;
    __shared__ float wts[32];
    __shared__ int shr[3];
    if (tid == 0) {
        int s = spans[2 * n], e = spans[2 * n + 1];
        s = min(max(s, 0), LEN - 1);
        e = min(max(e, 0), LEN - 1);
        int w = e - s + 1;
        if (w < 1) w = 1;
        if (w > MAXW) w = MAXW;
        shr[0] = s; shr[1] = e; shr[2] = w;
        g_s[n] = s; g_w[n] = w;
    }
    __syncthreads();
    int s = shr[0], e = shr[1], w = shr[2];
    if (warp == 0) {
        float v = (lane < w) ? g_tok[s + lane] : -1e30f;
        float mx = v;
        #pragma unroll
        for (int o = 16; o > 0; o >>= 1) mx = fmaxf(mx, __shfl_xor_sync(0xffffffffu, mx, o));
        float p = (lane < w) ? expf(v - mx) : 0.f;
        float sm = p;
        #pragma unroll
        for (int o = 16; o > 0; o >>= 1) sm += __shfl_xor_sync(0xffffffffu, sm, o);
        wts[lane] = p / sm;
    }
    __syncthreads();

    size_t bh = (size_t)n * KPAD;
    const float* hs = h + (size_t)s * HD;
    const float* he = h + (size_t)e * HD;
    for (int c = tid; c < HD; c += 128) {
        float acc = 0.f;
        for (int wp = 0; wp < w; wp++) acc += wts[wp] * h[(size_t)(s + wp) * HD + c];
        g_baseh[bh + c]          = __float2bfloat16(hs[c]);
        g_baseh[bh + HD + c]     = __float2bfloat16(he[c]);
        g_baseh[bh + 2 * HD + c] = __float2bfloat16(acc);
    }
    if (tid < 20)
        g_baseh[bh + 3 * HD + tid] = __float2bfloat16(width_emb[(w - 1) * 20 + tid]);
}

// ---------------- width-prior MLP (30 widths x 6 f-segments) ----------------
__global__ void width_scores(const float* __restrict__ wprior, const float* __restrict__ w0,
                             const float* __restrict__ b0, const float* __restrict__ w1)
{
    int w = blockIdx.x, seg = blockIdx.y;
    int tid = threadIdx.x;            // 256
    __shared__ float wv[20];
    __shared__ float red[256];
    if (tid < 20) wv[tid] = wprior[w * 20 + tid];
    __syncthreads();
    float acc = 0.f;
    int f0 = seg * 512;
    int f1 = min(f0 + 512, FFD);
    for (int f = f0 + tid; f < f1; f += 256) {
        float d = b0[f];
        #pragma unroll
        for (int k = 0; k < 20; k++) d += wv[k] * w0[k * FFD + f];
        acc += fmaxf(d, 0.f) * w1[f];
    }
    red[tid] = acc;
    __syncthreads();
    for (int o = 128; o > 0; o >>= 1) { if (tid < o) red[tid] += red[tid + o]; __syncthreads(); }
    if (tid == 0) g_wpart[w * 6 + seg] = red[0];
}

__global__ void m_init(const float* __restrict__ mb1, const float* __restrict__ wb1)
{
    int n = blockIdx.x * 256 + threadIdx.x;
    if (n >= NSP) return;
    int w = g_w[n] - 1;
    float acc = mb1[0] + wb1[0];
    #pragma unroll
    for (int c = 0; c < 6; c++) acc += g_wpart[w * 6 + c];
    g_m[n] = acc;
}

// ---------------- bf16 tensor-core GEMM, cp.async 4-stage, 2 CTAs/SM ----------------
// EPI 0: fused mention epilogue -> g_part
// EPI 1: fused fine epilogue    -> g_part  (+ uabA[i] + uabB[p] + feat[code])
// EPI 2: raw C (+optional bias) -> outC
template<int EPI>
__global__ __launch_bounds__(256, 2) void hgemm2(
    const __nv_bfloat16* __restrict__ A,
    const __nv_bfloat16* __restrict__ Bg, int ldb,
    const float* __restrict__ b0v, const float* __restrict__ w1v,
    float* __restrict__ outC, int ldc, int R, int maxC)
{
    extern __shared__ char smem[];
    __shared__ float rowsum[BM];
    __shared__ int sRi[BM], sRp[BM], sRc[BM];

    int tid = threadIdx.x;
    int lane = tid & 31, warp = tid >> 5;
    int wm = warp >> 2, wn = warp & 3;
    int row0 = blockIdx.y * BM, col0 = blockIdx.x * BN;

    if (tid < BM) {
        rowsum[tid] = 0.f;
        if (EPI == 1) {
            int r = row0 + tid;
            int i = r / CANT; if (i > KTOP - 1) i = KTOP - 1;
            int p = (r < PROWS) ? g_antpos[r] : 0;
            sRi[tid] = i; sRp[tid] = p;
            int same = (g_topspk[i] == g_topspk[p]) ? 1 : 0;
            int off = i - p; if (off < 0) off = 0;
            int bk = off >= 64 ? 9 : off >= 32 ? 8 : off >= 16 ? 7 : off >= 8 ? 6 : off >= 5 ? 5 : off;
            int ds = g_topseg[i] - g_topseg[p]; ds = ds < 0 ? 0 : (ds > 2 ? 2 : ds);
            sRc[tid] = (same * 10 + bk) * 3 + ds;
        }
    }
    __syncthreads();

    float acc[4][4][4];
    #pragma unroll
    for (int a = 0; a < 4; a++)
        #pragma unroll
        for (int b = 0; b < 4; b++)
            #pragma unroll
            for (int c = 0; c < 4; c++) acc[a][b][c] = 0.f;

    const int KT = KPAD / BKK;    // 73

    auto issue = [&](int kt) {
        int k0 = kt * BKK;
        char* sa = smem + (size_t)(kt % STAGES) * STAGE_BYTES;
        char* sb = sa + A_BYTES;
        #pragma unroll
        for (int v = 0; v < 2; v++) {
            int idx = tid + v * 256;
            int arow = idx >> 2, aseg = idx & 3;
            cp_async16(sa + (size_t)(arow * A_PITCH + aseg * 8) * 2,
                       A + (size_t)(row0 + arow) * KPAD + k0 + aseg * 8);
            int brow = idx >> 4, bseg = idx & 15;
            cp_async16(sb + (size_t)(brow * B_PITCH + bseg * 8) * 2,
                       Bg + (size_t)(k0 + brow) * ldb + col0 + bseg * 8);
        }
    };

    #pragma unroll
    for (int s = 0; s < STAGES - 1; s++) { issue(s); cp_commit(); }

    for (int kt = 0; kt < KT; kt++) {
        cp_wait<STAGES - 2>();
        __syncthreads();
        if (kt + STAGES - 1 < KT) issue(kt + STAGES - 1);
        cp_commit();

        int cur = kt % STAGES;
        const __nv_bfloat16 (*As)[A_PITCH] =
            (const __nv_bfloat16 (*)[A_PITCH])(smem + (size_t)cur * STAGE_BYTES);
        const __nv_bfloat16 (*Bs)[B_PITCH] =
            (const __nv_bfloat16 (*)[B_PITCH])(smem + (size_t)cur * STAGE_BYTES + A_BYTES);

        #pragma unroll
        for (int kk = 0; kk < BKK; kk += 16) {
            uint32_t af[4][4];
            #pragma unroll
            for (int mf = 0; mf < 4; mf++) {
                uint32_t addr = (uint32_t)__cvta_generic_to_shared(
                    &As[wm * 64 + mf * 16 + (lane & 15)][kk + ((lane >> 4) << 3)]);
                ldsm_x4(af[mf], addr);
            }
            uint32_t bfr[2][4];
            #pragma unroll
            for (int g = 0; g < 2; g++) {
                int krow = kk + (lane & 7) + ((lane & 8) ? 8 : 0);
                int bcol = wn * 32 + g * 16 + ((lane & 16) ? 8 : 0);
                uint32_t addr = (uint32_t)__cvta_generic_to_shared(&Bs[krow][bcol]);
                ldsm_x4_t(bfr[g], addr);
            }
            #pragma unroll
            for (int mf = 0; mf < 4; mf++)
                #pragma unroll
                for (int nf = 0; nf < 4; nf++)
                    mma_bf16(acc[mf][nf], af[mf], bfr[nf >> 1][(nf & 1) * 2],
                             bfr[nf >> 1][(nf & 1) * 2 + 1]);
        }
        __syncthreads();
    }

    if (EPI == 2) {
        #pragma unroll
        for (int mf = 0; mf < 4; mf++)
            #pragma unroll
            for (int rr = 0; rr < 2; rr++) {
                int r = row0 + wm * 64 + mf * 16 + (lane >> 2) + rr * 8;
                if (r >= R) continue;
                #pragma unroll
                for (int nf = 0; nf < 4; nf++) {
                    int f = col0 + wn * 32 + nf * 8 + (lane & 3) * 2;
                    #pragma unroll
                    for (int c = 0; c < 2; c++) {
                        if (f + c < maxC) {
                            float v = acc[mf][nf][rr * 2 + c];
                            if (b0v) v += b0v[f + c];
                            outC[(size_t)r * ldc + f + c] = v;
                        }
                    }
                }
            }
        return;
    }

    // fused epilogue: relu(acc + bias terms) * w1, reduce over block columns
    #pragma unroll
    for (int mf = 0; mf < 4; mf++)
        #pragma unroll
        for (int rr = 0; rr < 2; rr++) {
            int lrow = wm * 64 + mf * 16 + (lane >> 2) + rr * 8;
            const float* uA = nullptr; const float* uB = nullptr; const float* uF = nullptr;
            if (EPI == 1) {
                uA = g_uabA + (size_t)sRi[lrow] * FFP;
                uB = g_uabB + (size_t)sRp[lrow] * FFP;
                uF = g_feat + (size_t)sRc[lrow] * FFP;
            }
            float part = 0.f;
            #pragma unroll
            for (int nf = 0; nf < 4; nf++)
                #pragma unroll
                for (int c = 0; c < 2; c++) {
                    int f = col0 + wn * 32 + nf * 8 + (lane & 3) * 2 + c;
                    float v = acc[mf][nf][rr * 2 + c];
                    if (f < FFD) v += b0v[f];
                    if (EPI == 1) v += uA[f] + uB[f] + uF[f];
                    float w1f = (f < FFD) ? w1v[f] : 0.f;
                    part += fmaxf(v, 0.f) * w1f;
                }
            atomicAdd(&rowsum[lrow], part);
        }
    __syncthreads();
    if (tid < BM) {
        int r = row0 + tid;
        if (r < R) g_part[(size_t)r * NCB + blockIdx.x] = rowsum[tid];
    }
}

__global__ void mlp_reduce(const float* __restrict__ initv, int which, int R)
{
    int r = blockIdx.x * 256 + threadIdx.x;
    if (r >= R) return;
    float acc = 0.f;
    #pragma unroll
    for (int c = 0; c < NCB; c++) acc += g_part[(size_t)r * NCB + c];
    if (which) g_fine[r] = initv[0] + acc;
    else       g_m[r] += acc;
}

// ---------------- top-K mentions: 64-bit radix select in smem ----------------
__global__ void topk_mentions(const int* __restrict__ spk, const int* __restrict__ sent)
{
    extern __shared__ unsigned long long skeys[];   // NSP keys (64 KB)
    __shared__ int hist[256];
    __shared__ int tix[256];
    __shared__ unsigned long long s_pfx;
    __shared__ int s_tgt, s_cnt;
    int tid = threadIdx.x;            // 1024
    for (int i = tid; i < NSP; i += 1024) skeys[i] = make_key(g_m[i], (unsigned)i);
    if (tid == 0) { s_tgt = KTOP; s_pfx = 0ull; s_cnt = 0; }
    __syncthreads();

    for (int byte = 7; byte >= 0; byte--) {
        int shift = byte * 8;
        if (tid < 256) hist[tid] = 0;
        __syncthreads();
        unsigned long long pfx = s_pfx;
        for (int i = tid; i < NSP; i += 1024) {
            unsigned long long k = skeys[i];
            bool match = (byte == 7) || ((k >> (shift + 8)) == (pfx >> (shift + 8)));
            if (match) atomicAdd(&hist[(int)((k >> shift) & 255)], 1);
        }
        __syncthreads();
        if (tid == 0) {
            int cum = 0, v = 255;
            for (; v > 0; v--) { if (cum + hist[v] >= s_tgt) break; cum += hist[v]; }
            s_tgt -= cum;
            s_pfx = pfx | ((unsigned long long)(unsigned)v << shift);
        }
        __syncthreads();
    }
    unsigned long long thr = s_pfx;
    for (int i = tid; i < NSP; i += 1024) {
        if (skeys[i] >= thr) {
            int pos = atomicAdd(&s_cnt, 1);
            if (pos < 256) tix[pos] = key_idx(skeys[i]);
        }
    }
    __syncthreads();
    for (int t = tid; t < 256; t += 1024) if (t >= KTOP) tix[t] = 0x7FFFFFFF;
    __syncthreads();
    for (unsigned k = 2; k <= 256; k <<= 1)
        for (unsigned j = k >> 1; j > 0; j >>= 1) {
            for (unsigned t = tid; t < 256; t += 1024) {
                unsigned ixj = t ^ j;
                if (ixj > t) {
                    int a = tix[t], b = tix[ixj];
                    bool asc = ((t & k) == 0);
                    if (asc ? (a > b) : (a < b)) { tix[t] = b; tix[ixj] = a; }
                }
            }
            __syncthreads();
        }
    if (tid < KTOP) {
        int idx = tix[tid];
        g_topidx[tid] = idx;
        g_topm[tid]   = g_m[idx];
        int s = g_s[idx];
        g_topspk[tid] = spk[s];
        g_topseg[tid] = sent[s];
    }
}

__global__ void gather_topbase()
{
    int i = blockIdx.x;               // KTOP blocks
    const __nv_bfloat16* src = g_baseh + (size_t)g_topidx[i] * KPAD;
    float* dst = g_topbase + (size_t)i * MD;
    __nv_bfloat16* dsh = g_topbaseh + (size_t)i * KPAD;
    for (int d = threadIdx.x; d < MD; d += 256) {
        __nv_bfloat16 v = src[d];
        dst[d] = __bfloat162float(v);
        dsh[d] = v;
    }
}

// ---------------- coarse pair scores ----------------
__global__ void cp_kernel()
{
    __shared__ float As[16][17];
    __shared__ float Bs[16][17];
    int tx = threadIdx.x, ty = threadIdx.y;
    int i0 = blockIdx.y * 16, j0 = blockIdx.x * 16;
    int i = i0 + ty, j = j0 + tx;
    float acc = 0.f;
    for (int k0 = 0; k0 < MD; k0 += 16) {
        int k = k0 + tx;
        As[ty][tx] = (i0 + ty < KTOP && k < MD) ? g_src[(size_t)(i0 + ty) * MD + k] : 0.f;
        Bs[ty][tx] = (j0 + ty < KTOP && k < MD) ? g_topbase[(size_t)(j0 + ty) * MD + k] : 0.f;
        __syncthreads();
        #pragma unroll
        for (int kk = 0; kk < 16; kk++) acc += As[ty][kk] * Bs[tx][kk];
        __syncthreads();
    }
    if (i < KTOP && j < KTOP) {
        float v = acc + g_topm[i] + g_topm[j];
        if (j >= i) v = NEG9;
        g_cp[i * KTOP + j] = v;
    }
}

// ---------------- per-row top-C antecedents ----------------
__global__ void topc()
{
    int i = blockIdx.x;
    int tid = threadIdx.x;            // 128
    __shared__ unsigned long long keys[256];
    for (int t = tid; t < 256; t += 128)
        keys[t] = (t < KTOP) ? make_key(g_cp[i * KTOP + t], (unsigned)t) : 0ull;
    __syncthreads();
    for (unsigned k = 2; k <= 256; k <<= 1)
        for (unsigned j = k >> 1; j > 0; j >>= 1) {
            for (unsigned t = tid; t < 256; t += 128) {
                unsigned ixj = t ^ j;
                if (ixj > t) {
                    unsigned long long a = keys[t], b = keys[ixj];
                    bool desc = ((t & k) == 0);
                    if (desc ? (a < b) : (a > b)) { keys[t] = b; keys[ixj] = a; }
                }
            }
            __syncthreads();
        }
    if (tid < CANT) {
        int pos = key_idx(keys[tid]);
        g_antpos[i * CANT + tid] = pos;
        g_antsc[i * CANT + tid] = g_cp[i * KTOP + pos];
    }
}

// ---------------- pairwise product rows (bf16) ----------------
__global__ void pack_prod()
{
    int r = blockIdx.x;               // PPAD
    int tid = threadIdx.x;            // 256
    int i = r / CANT; if (i > KTOP - 1) i = KTOP - 1;
    int p = (r < PROWS) ? g_antpos[r] : 0;
    const uint4* a = (const uint4*)(g_topbaseh + (size_t)i * KPAD);
    const uint4* b = (const uint4*)(g_topbaseh + (size_t)p * KPAD);
    uint4* o = (uint4*)(g_pairh + (size_t)r * KPAD);
    for (int v = tid; v < KPAD / 8; v += 256) {
        uint4 va = a[v], vb = b[v], vo;
        __nv_bfloat162* pa = (__nv_bfloat162*)&va;
        __nv_bfloat162* pb = (__nv_bfloat162*)&vb;
        __nv_bfloat162* po = (__nv_bfloat162*)&vo;
        #pragma unroll
        for (int q = 0; q < 4; q++) po[q] = __hmul2(pa[q], pb[q]);
        o[v] = vo;
    }
}

// ---------------- feature table projections ----------------
__global__ void featproj(const float* __restrict__ aw0,
                         const float* __restrict__ spk_emb, const float* __restrict__ gen_emb,
                         const float* __restrict__ dist_emb, const float* __restrict__ seg_emb)
{
    int row = blockIdx.x;             // 22
    int tid = threadIdx.x;            // 256
    const float* emb; int off;
    if (row < 2)       { emb = spk_emb  + row * 20;        off = 0; }
    else if (row < 9)  { emb = gen_emb  + (row - 2) * 20;  off = 20; }
    else if (row < 19) { emb = dist_emb + (row - 9) * 20;  off = 40; }
    else               { emb = seg_emb  + (row - 19) * 20; off = 60; }
    __shared__ float ev[20];
    if (tid < 20) ev[tid] = emb[tid];
    __syncthreads();
    for (int f = tid; f < FFP; f += 256) {
        float acc = 0.f;
        if (f < FFD) {
            #pragma unroll
            for (int k = 0; k < 20; k++)
                acc += ev[k] * aw0[(size_t)(3 * MD + off + k) * FFD + f];
        }
        g_ftab[(size_t)row * FFP + f] = acc;
    }
}

__global__ void featcomb(const int* __restrict__ gen_ids)
{
    int code = blockIdx.x;            // 60
    int tid = threadIdx.x;            // 256
    int s = code / 30, bk = (code / 3) % 10, ds = code % 3;
    int g = gen_ids[0];
    for (int f = tid; f < FFP; f += 256)
        g_feat[(size_t)code * FFP + f] =
            g_ftab[(size_t)s * FFP + f] + g_ftab[(size_t)(2 + g) * FFP + f] +
            g_ftab[(size_t)(9 + bk) * FFP + f] + g_ftab[(size_t)(19 + ds) * FFP + f];
}

// ---------------- final output ----------------
__global__ void final_out(float* __restrict__ out, const float* __restrict__ dummy)
{
    int i = blockIdx.x;
    int tid = threadIdx.x;            // 64
    if (tid == 0) out[i * (CANT + 1)] = dummy[0];
    if (tid < CANT) {
        int p = g_antpos[i * CANT + tid];
        bool valid = p < i;
        out[i * (CANT + 1) + 1 + tid] =
            valid ? (g_antsc[i * CANT + tid] + g_fine[i * CANT + tid] * 2.0f) : NEG9;
    }
}

// ---------------- launch ----------------
extern "C" void kernel_launch(void* const* d_in, const int* in_sizes, int n_in,
                              void* d_out, int out_size)
{
    const float* h          = (const float*)d_in[0];
    const int*   spans      = (const int*)  d_in[1];
    const int*   spk_ids    = (const int*)  d_in[2];
    const int*   gen_ids    = (const int*)  d_in[3];
    const int*   sent_map   = (const int*)  d_in[4];
    const float* w_head     = (const float*)d_in[5];
    const float* b_head     = (const float*)d_in[6];
    const float* width_emb  = (const float*)d_in[7];
    const float* width_prior= (const float*)d_in[8];
    const float* speaker_emb= (const float*)d_in[9];
    const float* segment_emb= (const float*)d_in[10];
    const float* genre_emb  = (const float*)d_in[11];
    const float* dist_emb   = (const float*)d_in[12];
    const float* mention_w0 = (const float*)d_in[13];
    const float* mention_b0 = (const float*)d_in[14];
    const float* mention_w1 = (const float*)d_in[15];
    const float* mention_b1 = (const float*)d_in[16];
    const float* width_w0   = (const float*)d_in[17];
    const float* width_b0   = (const float*)d_in[18];
    const float* width_w1   = (const float*)d_in[19];
    const float* width_b1   = (const float*)d_in[20];
    const float* c2_w       = (const float*)d_in[21];
    const float* c2_b       = (const float*)d_in[22];
    const float* ant_w0     = (const float*)d_in[23];
    const float* ant_b0     = (const float*)d_in[24];
    const float* ant_w1     = (const float*)d_in[25];
    const float* ant_b1     = (const float*)d_in[26];
    const float* dummy_bias = (const float*)d_in[27];
    float* out = (float*)d_out;

    cudaFuncSetAttribute(hgemm2<0>, cudaFuncAttributeMaxDynamicSharedMemorySize, DSMEM);
    cudaFuncSetAttribute(hgemm2<1>, cudaFuncAttributeMaxDynamicSharedMemorySize, DSMEM);
    cudaFuncSetAttribute(hgemm2<2>, cudaFuncAttributeMaxDynamicSharedMemorySize, DSMEM);
    cudaFuncSetAttribute(topk_mentions, cudaFuncAttributeMaxDynamicSharedMemorySize, NSP * 8);

    void *pBaseh, *pW0h, *pAw0h, *pC2h, *pPairh, *pTopbh, *pUA, *pUB, *pSrc;
    cudaGetSymbolAddress(&pBaseh, g_baseh);
    cudaGetSymbolAddress(&pW0h,   g_w0h);
    cudaGetSymbolAddress(&pAw0h,  g_aw0h);
    cudaGetSymbolAddress(&pC2h,   g_c2h);
    cudaGetSymbolAddress(&pPairh, g_pairh);
    cudaGetSymbolAddress(&pTopbh, g_topbaseh);
    cudaGetSymbolAddress(&pUA,    g_uabA);
    cudaGetSymbolAddress(&pUB,    g_uabB);
    cudaGetSymbolAddress(&pSrc,   g_src);
    const __nv_bfloat16* baseh = (const __nv_bfloat16*)pBaseh;
    const __nv_bfloat16* w0h   = (const __nv_bfloat16*)pW0h;
    const __nv_bfloat16* aw0h  = (const __nv_bfloat16*)pAw0h;
    const __nv_bfloat16* c2h   = (const __nv_bfloat16*)pC2h;
    const __nv_bfloat16* pairh = (const __nv_bfloat16*)pPairh;
    const __nv_bfloat16* topbh = (const __nv_bfloat16*)pTopbh;

    // weight conversions
    {
        size_t n1 = (size_t)KPAD * FFP;
        conv_w0<<<(unsigned)((n1 + 255) / 256), 256>>>(mention_w0);
        conv_aw0<<<(unsigned)((3 * n1 + 255) / 256), 256>>>(ant_w0);
        size_t n2 = (size_t)KPAD * C2N;
        conv_c2<<<(unsigned)((n2 + 255) / 256), 256>>>(c2_w);
    }

    tok_score<<<LEN / 32, 1024>>>(h, w_head, b_head);
    span_prep<<<NSP, 128>>>(h, spans, width_emb);
    width_scores<<<dim3(MAXW, 6), 256>>>(width_prior, width_w0, width_b0, width_w1);
    m_init<<<(NSP + 255) / 256, 256>>>(mention_b1, width_b1);

    // mention MLP
    hgemm2<0><<<dim3(NCB, NSP / BM), 256, DSMEM>>>(
        baseh, w0h, FFP, mention_b0, mention_w1, nullptr, 0, NSP, FFP);
    mlp_reduce<<<(NSP + 255) / 256, 256>>>(nullptr, 0, NSP);

    topk_mentions<<<1, 1024, NSP * 8>>>(spk_ids, sent_map);
    gather_topbase<<<KTOP, 256>>>();

    // src = top_base @ c2_w + c2_b
    hgemm2<2><<<dim3(C2N / BN, 2), 256, DSMEM>>>(
        topbh, c2h, C2N, c2_b, nullptr, (float*)pSrc, MD, KTOP, MD);

    dim3 gc((KTOP + 15) / 16, (KTOP + 15) / 16);
    cp_kernel<<<gc, dim3(16, 16)>>>();
    topc<<<KTOP, 128>>>();

    featproj<<<22, 256>>>(ant_w0, speaker_emb, genre_emb, dist_emb, segment_emb);
    featcomb<<<60, 256>>>(gen_ids);

    // UA = top_base @ W0a, UB = top_base @ W0b
    hgemm2<2><<<dim3(NCB, 2), 256, DSMEM>>>(
        topbh, aw0h, FFP, nullptr, nullptr, (float*)pUA, FFP, KTOP, FFP);
    hgemm2<2><<<dim3(NCB, 2), 256, DSMEM>>>(
        topbh, aw0h + SECT, FFP, nullptr, nullptr, (float*)pUB, FFP, KTOP, FFP);

    pack_prod<<<PPAD, 256>>>();

    // fine pairwise MLP
    hgemm2<1><<<dim3(NCB, PPAD / BM), 256, DSMEM>>>(
        pairh, aw0h + 2 * SECT, FFP, ant_b0, ant_w1, nullptr, 0, PPAD, FFP);
    mlp_reduce<<<(PPAD + 255) / 256, 256>>>(ant_b1, 1, PPAD);

    final_out<<<KTOP, 64>>>(out, dummy_bias);
}